// round 2
// baseline (speedup 1.0000x reference)
#include <cuda_runtime.h>
#include <cstdint>

// Problem constants (fixed shapes)
#define NN 32768        // B*H*W = 32*32*32 rows
#define DD 256          // embedding dim
#define KK 8192         // codebook size
#define BM 128          // rows per CTA
#define BN 128          // codes per chunk
#define BKc 32          // d-chunk

#define OUT_OFF  0
#define LOSS_OFF 8388608
#define IDX_OFF  8388609

__device__ float  g_e2[KK];
__device__ float  g_xs[NN];
__device__ double g_part[NN / BM];   // 256 CTA partials

// ---------------------------------------------------------------------------
// packed fp32x2 FMA (Blackwell dual-FP32 path; ptxas will not auto-fuse)
// ---------------------------------------------------------------------------
__device__ __forceinline__ float2 ffma2(float2 a, float2 b, float2 c) {
    union U { float2 f; unsigned long long u; };
    U A, B, C, R;
    A.f = a; B.f = b; C.f = c;
    asm("fma.rn.f32x2 %0, %1, %2, %3;"
        : "=l"(R.u) : "l"(A.u), "l"(B.u), "l"(C.u));
    return R.f;
}

// ---------------------------------------------------------------------------
// Precompute ||e_k||^2  (one warp per code row, coalesced)
// ---------------------------------------------------------------------------
__global__ void vq_e2(const float* __restrict__ emb) {
    int gw = (blockIdx.x * blockDim.x + threadIdx.x) >> 5;
    int l  = threadIdx.x & 31;
    if (gw >= KK) return;
    const float* e = emb + (size_t)gw * DD;
    float s = 0.f;
#pragma unroll
    for (int t = 0; t < DD / 32; t++) {
        float v = e[l + 32 * t];
        s = fmaf(v, v, s);
    }
#pragma unroll
    for (int o = 16; o > 0; o >>= 1) s += __shfl_xor_sync(0xffffffffu, s, o);
    if (l == 0) g_e2[gw] = s;
}

// ---------------------------------------------------------------------------
// Precompute ||z_n||^2 (x is NCHW => [d][n]-major: fully coalesced over n)
// ---------------------------------------------------------------------------
__global__ void vq_xs(const float* __restrict__ x) {
    int n = blockIdx.x * blockDim.x + threadIdx.x;
    if (n >= NN) return;
    int b = n >> 10, c = n & 1023;
    const float* xb = x + (size_t)b * (DD * 1024) + c;
    float s = 0.f;
#pragma unroll 8
    for (int d = 0; d < DD; d++) {
        float v = xb[d * 1024];
        s = fmaf(v, v, s);
    }
    g_xs[n] = s;
}

// ---------------------------------------------------------------------------
// Main: fused distance-GEMM + argmin + gather/ST output + loss partial
// ---------------------------------------------------------------------------
__global__ void __launch_bounds__(256, 2)
vq_main(const float* __restrict__ x, const float* __restrict__ emb,
        float* __restrict__ out) {
    __shared__ __align__(16) float As[BKc * BM];        // 16 KB  [dd][m]
    __shared__ __align__(16) float Bs[BN * (BKc + 1)];  // 16.5 KB [kk][dd], pad 33
    __shared__ float e2s[BN];
    __shared__ int   sidx[BM];

    const int tid = threadIdx.x;
    const int tx  = tid & 15;      // 16 col-groups
    const int ty  = tid >> 4;      // 16 row-groups (8 rows each)
    const int n0  = blockIdx.x * BM;
    const int b   = n0 >> 10;
    const int col0 = n0 & 1023;
    const float* xb = x + (size_t)b * (DD * 1024);

    float s_m[8];
#pragma unroll
    for (int i = 0; i < 8; i++) s_m[i] = g_xs[n0 + ty * 8 + i];

    float best_v[8];
    int   best_i[8];
#pragma unroll
    for (int i = 0; i < 8; i++) { best_v[i] = __int_as_float(0x7f800000); best_i[i] = 0; }

    for (int kt = 0; kt < KK / BN; kt++) {
        const int k0 = kt * BN;
        float2 acc[4][8];
#pragma unroll
        for (int mp = 0; mp < 4; mp++)
#pragma unroll
            for (int j = 0; j < 8; j++) acc[mp][j] = make_float2(0.f, 0.f);

        for (int dt = 0; dt < DD / BKc; dt++) {
            const int d0 = dt * BKc;
            __syncthreads();
            if (dt == 0 && tid < BN) e2s[tid] = g_e2[k0 + tid];
            // load A tile: 32 dd x 128 m (x already [d][n]-major, no transpose)
#pragma unroll
            for (int p = 0; p < 4; p++) {
                int i  = tid + p * 256;
                int dd = i >> 5, m4 = i & 31;
                float4 v = *(const float4*)(xb + (size_t)(d0 + dd) * 1024 + col0 + m4 * 4);
                *(float4*)(&As[dd * BM + m4 * 4]) = v;
            }
            // load B tile: 128 kk x 32 dd, natural layout, pad-33 rows
#pragma unroll
            for (int p = 0; p < 4; p++) {
                int i  = tid + p * 256;
                int kk = i >> 3, dq = i & 7;
                float4 v = *(const float4*)(emb + (size_t)(k0 + kk) * DD + d0 + dq * 4);
                float* bp = &Bs[kk * (BKc + 1) + dq * 4];
                bp[0] = v.x; bp[1] = v.y; bp[2] = v.z; bp[3] = v.w;
            }
            __syncthreads();

#pragma unroll 4
            for (int dd = 0; dd < BKc; dd++) {
                float2 a[4];
#pragma unroll
                for (int mp = 0; mp < 4; mp++)
                    a[mp] = *(const float2*)&As[dd * BM + ty * 8 + mp * 2];
                float bv[8];
#pragma unroll
                for (int j = 0; j < 8; j++)
                    bv[j] = Bs[(tx + 16 * j) * (BKc + 1) + dd];
#pragma unroll
                for (int j = 0; j < 8; j++) {
                    float2 bb = make_float2(bv[j], bv[j]);
#pragma unroll
                    for (int mp = 0; mp < 4; mp++)
                        acc[mp][j] = ffma2(a[mp], bb, acc[mp][j]);
                }
            }
        }

        // per-chunk argmin epilogue. Exact ref rounding:
        //   dist = fl( fl(s + e2) - fl(2*dot) ), ties -> lowest k (ascending scan, strict <)
#pragma unroll
        for (int j = 0; j < 8; j++) {
            const int   kg  = k0 + tx + 16 * j;
            const float e2k = e2s[tx + 16 * j];
#pragma unroll
            for (int mp = 0; mp < 4; mp++) {
                {
                    float t = __fadd_rn(s_m[2 * mp], e2k);
                    float v = __fsub_rn(t, __fmul_rn(2.0f, acc[mp][j].x));
                    bool p = v < best_v[2 * mp];
                    best_v[2 * mp] = p ? v : best_v[2 * mp];
                    best_i[2 * mp] = p ? kg : best_i[2 * mp];
                }
                {
                    float t = __fadd_rn(s_m[2 * mp + 1], e2k);
                    float v = __fsub_rn(t, __fmul_rn(2.0f, acc[mp][j].y));
                    bool p = v < best_v[2 * mp + 1];
                    best_v[2 * mp + 1] = p ? v : best_v[2 * mp + 1];
                    best_i[2 * mp + 1] = p ? kg : best_i[2 * mp + 1];
                }
            }
        }
    }

    // cross-thread argmin reduction (16 tx per row), idx-aware tie-break
    __syncthreads();
    float* rv = As;                       // 2048 floats, aliases As
    int*   ri = (int*)Bs;                 // 2048 ints,  aliases Bs
#pragma unroll
    for (int i = 0; i < 8; i++) {
        int r = ty * 8 + i;
        rv[r * 16 + tx] = best_v[i];
        ri[r * 16 + tx] = best_i[i];
    }
    __syncthreads();
    if (tid < BM) {
        int r = tid;
        float bv = rv[r * 16];
        int   bi = ri[r * 16];
#pragma unroll
        for (int t = 1; t < 16; t++) {
            float v = rv[r * 16 + t];
            int   ii = ri[r * 16 + t];
            bool p = (v < bv) || (v == bv && ii < bi);
            bv = p ? v : bv;
            bi = p ? ii : bi;
        }
        sidx[r] = bi;
        out[IDX_OFF + n0 + r] = (float)bi;   // idx as float
    }
    __syncthreads();

    // gather + straight-through output + loss partial
    // out[b,d,h,w] = fl(xp + fl(q - xp));  loss term = fl(q-xp)^2 (fp32 square)
    const int r  = tid & 127;
    const int dh = tid >> 7;
    const int er = sidx[r];
    const float* embrow = emb + (size_t)er * DD;
    const float* xr = xb + col0 + r;
    float* outr = out + OUT_OFF + (size_t)b * (DD * 1024) + col0 + r;
    double lsum = 0.0;
#pragma unroll 4
    for (int dj = 0; dj < 128; dj++) {
        int d = dh * 128 + dj;
        float xp = xr[d * 1024];
        float q  = embrow[d];
        float dl = __fsub_rn(q, xp);
        outr[d * 1024] = __fadd_rn(xp, dl);
        float sq = __fmul_rn(dl, dl);
        lsum += (double)sq;
    }

    // deterministic block tree-reduce of the double partial
    __syncthreads();
    double* dr = (double*)As;             // 2 KB, aliases As
    dr[tid] = lsum;
    __syncthreads();
    for (int sft = 128; sft > 0; sft >>= 1) {
        if (tid < sft) dr[tid] += dr[tid + sft];
        __syncthreads();
    }
    if (tid == 0) g_part[blockIdx.x] = dr[0];
}

// ---------------------------------------------------------------------------
// Finalize loss: deterministic serial sum of 256 partials
//   e_latent == q_latent numerically => loss = fl(L + fl(0.25*L))
// ---------------------------------------------------------------------------
__global__ void vq_final(float* __restrict__ out) {
    if (blockIdx.x == 0 && threadIdx.x == 0) {
        double s = 0.0;
        for (int i = 0; i < NN / BM; i++) s += g_part[i];
        float L = (float)(s / (double)(NN * DD));
        out[LOSS_OFF] = __fadd_rn(L, __fmul_rn(0.25f, L));
    }
}

extern "C" void kernel_launch(void* const* d_in, const int* in_sizes, int n_in,
                              void* d_out, int out_size) {
    const float* x   = (const float*)d_in[0];
    const float* emb = (const float*)d_in[1];
    float* out = (float*)d_out;
    vq_e2  <<<KK * 32 / 256, 256>>>(emb);
    vq_xs  <<<NN / 256,      256>>>(x);
    vq_main<<<NN / BM,       256>>>(x, emb, out);
    vq_final<<<1, 32>>>(out);
}

// round 6
// speedup vs baseline: 1.3612x; 1.3612x over previous
#include <cuda_runtime.h>
#include <cstdint>

// -------------------------- problem constants ------------------------------
#define NN 32768        // rows (B*H*W)
#define DD 256          // embedding dim
#define KK 8192         // codebook size
#define BM 128          // rows per CTA
#define BN 256          // codes per n-tile
#define NTILES (KK / BN)            // 32
#define NCHUNK 24                   // K' = 768 = 24 chunks of 32
#define NSTG (NTILES * NCHUNK)      // 768 stages
#define NCTA (NN / BM)              // 256

#define OUT_OFF  0
#define LOSS_OFF 8388608
#define IDX_OFF  8388609

#define STG_BYTES 49152   // A 16 KB + B 32 KB
#define B_OFF     16384
#define SMEM_DYN  (4 * STG_BYTES)   // 196608

__device__ float  g_e2[KK];
__device__ float  g_xs[NN];
__device__ double g_part[NCTA];
// tf32-split operands, chunk-major [chunk][row][32 floats]
// chunks 0-7 = hi (d 0..255), 8-15 = lo
__device__ __align__(16) float g_Axf[(size_t)16 * NN * 32];   // 67 MB
__device__ __align__(16) float g_Ebf[(size_t)16 * KK * 32];   // 16.8 MB

// ---------------------------- asm helpers ----------------------------------
__device__ __forceinline__ uint32_t smem_u32(const void* p) {
    uint32_t a;
    asm("{ .reg .u64 t; cvta.to.shared.u64 t, %1; cvt.u32.u64 %0, t; }" : "=r"(a) : "l"(p));
    return a;
}
// NOTE: cvt.rna.tf32.f32 requires a .b32 destination (R5 fix: "=r", not "=f")
__device__ __forceinline__ float to_tf32(float a) {
    uint32_t r;
    asm("cvt.rna.tf32.f32 %0, %1;" : "=r"(r) : "f"(a));
    return __uint_as_float(r);
}
#define CPA(dst, src) asm volatile("cp.async.cg.shared.global [%0], [%1], 16;" :: "r"(dst), "l"(src))
#define CPC()         asm volatile("cp.async.commit_group;" ::: "memory")
#define CPW(n)        asm volatile("cp.async.wait_group %0;" :: "n"(n) : "memory")

__device__ __forceinline__ void ldsm4(uint32_t* r, uint32_t addr) {
    asm volatile("ldmatrix.sync.aligned.m8n8.x4.shared.b16 {%0,%1,%2,%3}, [%4];"
        : "=r"(r[0]), "=r"(r[1]), "=r"(r[2]), "=r"(r[3]) : "r"(addr));
}
__device__ __forceinline__ void mma_tf32(float* c, const uint32_t* a, const uint32_t* b) {
    asm volatile("mma.sync.aligned.m16n8k8.row.col.f32.tf32.tf32.f32 "
        "{%0,%1,%2,%3}, {%4,%5,%6,%7}, {%8,%9}, {%0,%1,%2,%3};"
        : "+f"(c[0]), "+f"(c[1]), "+f"(c[2]), "+f"(c[3])
        : "r"(a[0]), "r"(a[1]), "r"(a[2]), "r"(a[3]), "r"(b[0]), "r"(b[1]));
}

// ---------------------------------------------------------------------------
// prep kernels
// ---------------------------------------------------------------------------
__global__ void vq_e2(const float* __restrict__ emb) {
    int gw = (blockIdx.x * blockDim.x + threadIdx.x) >> 5;
    int l  = threadIdx.x & 31;
    if (gw >= KK) return;
    const float* e = emb + (size_t)gw * DD;
    float s = 0.f;
#pragma unroll
    for (int t = 0; t < DD / 32; t++) { float v = e[l + 32 * t]; s = fmaf(v, v, s); }
#pragma unroll
    for (int o = 16; o > 0; o >>= 1) s += __shfl_xor_sync(0xffffffffu, s, o);
    if (l == 0) g_e2[gw] = s;
}

__global__ void vq_xs(const float* __restrict__ x) {
    int n = blockIdx.x * blockDim.x + threadIdx.x;
    if (n >= NN) return;
    int b = n >> 10, c = n & 1023;
    const float* xb = x + (size_t)b * (DD * 1024) + c;
    float s = 0.f;
#pragma unroll 8
    for (int d = 0; d < DD; d++) { float v = xb[(size_t)d * 1024]; s = fmaf(v, v, s); }
    g_xs[n] = s;
}

// x split: grid 1024 = 8 d-chunks x 128 row-blocks(256); smem transpose
__global__ void vq_split_x(const float* __restrict__ x) {
    __shared__ float sx[32][257];
    const int t  = threadIdx.x;
    const int dc = blockIdx.x & 7;
    const int nb = blockIdx.x >> 3;
    const int n0 = nb * 256;
    const int b  = n0 >> 10, hw0 = n0 & 1023;
    const float* xb = x + (size_t)b * (DD * 1024) + (size_t)(dc * 32) * 1024 + hw0;
#pragma unroll
    for (int dd = 0; dd < 32; dd++) sx[dd][t] = xb[(size_t)dd * 1024 + t];
    __syncthreads();
    float* dh = g_Axf + ((size_t)dc * NN + n0 + t) * 32;
    float* dl = g_Axf + ((size_t)(dc + 8) * NN + n0 + t) * 32;
#pragma unroll
    for (int q = 0; q < 8; q++) {
        float4 hv, lv;
        { float v = sx[4 * q + 0][t]; hv.x = to_tf32(v); lv.x = to_tf32(__fsub_rn(v, hv.x)); }
        { float v = sx[4 * q + 1][t]; hv.y = to_tf32(v); lv.y = to_tf32(__fsub_rn(v, hv.y)); }
        { float v = sx[4 * q + 2][t]; hv.z = to_tf32(v); lv.z = to_tf32(__fsub_rn(v, hv.z)); }
        { float v = sx[4 * q + 3][t]; hv.w = to_tf32(v); lv.w = to_tf32(__fsub_rn(v, hv.w)); }
        *(float4*)(dh + 4 * q) = hv;
        *(float4*)(dl + 4 * q) = lv;
    }
}

// emb split: 1 warp per code row
__global__ void vq_split_e(const float* __restrict__ emb) {
    int wid = threadIdx.x >> 5, lane = threadIdx.x & 31;
    int k = blockIdx.x * 8 + wid;
    const float* er = emb + (size_t)k * DD;
#pragma unroll
    for (int c = 0; c < 8; c++) {
        float v  = er[c * 32 + lane];
        float hi = to_tf32(v);
        float lo = to_tf32(__fsub_rn(v, hi));
        g_Ebf[((size_t)c * KK + k) * 32 + lane] = hi;
        g_Ebf[((size_t)(c + 8) * KK + k) * 32 + lane] = lo;
    }
}

// ---------------------------------------------------------------------------
// pipeline: issue one stage (A 16 KB + B 32 KB, XOR-swizzled granules)
// ---------------------------------------------------------------------------
__device__ __forceinline__ void issue(uint32_t sb, int slot, int g, int rt, int tid) {
    const int ti = g / NCHUNK, c = g - ti * NCHUNK;
    const int achk = (c < 16) ? (c & 7) : (c - 8);
    const int bchk = (c < 16) ? c : (c - 16);
    const char* aSrc = (const char*)g_Axf + ((size_t)achk * NN + (size_t)rt * BM) * 128;
    const char* bSrc = (const char*)g_Ebf + ((size_t)bchk * KK + (size_t)ti * BN) * 128;
    const uint32_t aDst = sb + slot * STG_BYTES;
    const uint32_t bDst = aDst + B_OFF;
#pragma unroll
    for (int p = 0; p < 4; p++) {
        int i = tid + p * 256, row = i >> 3, gg = i & 7;
        CPA(aDst + row * 128 + ((gg ^ (row & 7)) << 4), aSrc + (size_t)i * 16);
    }
#pragma unroll
    for (int p = 0; p < 8; p++) {
        int i = tid + p * 256, row = i >> 3, gg = i & 7;
        CPA(bDst + row * 128 + ((gg ^ (row & 7)) << 4), bSrc + (size_t)i * 16);
    }
}

// consume one stage: 4 k-steps of (12 ldmatrix.x4 + 32 mma)
__device__ __forceinline__ void consume(uint32_t aS, uint32_t bS, int wm, int wn,
                                        int lane, float (&acc)[4][8][4]) {
    const int grp = lane >> 3;
#pragma unroll
    for (int ks = 0; ks < 4; ks++) {
        uint32_t a[4][4];
#pragma unroll
        for (int mf = 0; mf < 4; mf++) {
            int row = wm * 64 + mf * 16 + (lane & 7) + (grp & 1) * 8;
            int gg  = 2 * ks + (grp >> 1);
            ldsm4(a[mf], aS + row * 128 + ((gg ^ (row & 7)) << 4));
        }
        uint32_t bfr[8][2];
#pragma unroll
        for (int nf2 = 0; nf2 < 4; nf2++) {
            int row = wn * 64 + nf2 * 16 + (lane & 7) + (grp >> 1) * 8;
            int gg  = 2 * ks + (grp & 1);
            uint32_t r[4];
            ldsm4(r, bS + row * 128 + ((gg ^ (row & 7)) << 4));
            bfr[2 * nf2][0] = r[0]; bfr[2 * nf2][1] = r[1];
            bfr[2 * nf2 + 1][0] = r[2]; bfr[2 * nf2 + 1][1] = r[3];
        }
#pragma unroll
        for (int mf = 0; mf < 4; mf++)
#pragma unroll
            for (int nf = 0; nf < 8; nf++)
                mma_tf32(acc[mf][nf], a[mf], bfr[nf]);
    }
}

// ---------------------------------------------------------------------------
// main fused kernel
// ---------------------------------------------------------------------------
__global__ void __launch_bounds__(256)
vq_main(const float* __restrict__ x, const float* __restrict__ emb,
        float* __restrict__ out)
{
    extern __shared__ __align__(16) char smem[];
    const uint32_t sb = smem_u32(smem);
    const int tid = threadIdx.x, lane = tid & 31, wid = tid >> 5;
    const int wm = wid & 1, wn = wid >> 1;            // 2m x 4n warps
    const int rt = blockIdx.x;
    const int n0 = rt * BM, b = n0 >> 10, col0 = n0 & 1023;

    float xs8[8];
#pragma unroll
    for (int mf = 0; mf < 4; mf++)
#pragma unroll
        for (int h = 0; h < 2; h++)
            xs8[mf * 2 + h] = g_xs[n0 + wm * 64 + mf * 16 + (lane >> 2) + 8 * h];

    float acc[4][8][4];
#pragma unroll
    for (int mf = 0; mf < 4; mf++)
#pragma unroll
        for (int nf = 0; nf < 8; nf++)
#pragma unroll
            for (int r = 0; r < 4; r++) acc[mf][nf][r] = 0.f;

    float best_v[8]; int best_i[8];
#pragma unroll
    for (int s = 0; s < 8; s++) { best_v[s] = __int_as_float(0x7f800000); best_i[s] = 0; }

    float2 e2f[8];

    issue(sb, 0, 0, rt, tid); CPC();
    issue(sb, 1, 1, rt, tid); CPC();
    issue(sb, 2, 2, rt, tid); CPC();

#pragma unroll 1
    for (int g = 0; g < NSTG; g++) {
        CPW(2);
        __syncthreads();
        if (g + 3 < NSTG) issue(sb, (g + 3) & 3, g + 3, rt, tid);
        CPC();

        const int ti = g / NCHUNK, c = g - ti * NCHUNK;
        const int k0 = ti * BN;
        if (c == 0) {
#pragma unroll
            for (int nf = 0; nf < 8; nf++)
                e2f[nf] = *(const float2*)&g_e2[k0 + wn * 64 + nf * 8 + 2 * (lane & 3)];
        }

        const uint32_t aS = sb + (g & 3) * STG_BYTES;
        consume(aS, aS + B_OFF, wm, wn, lane, acc);

        if (c == NCHUNK - 1) {
            // dist = fl( fl(xs+e2) - 2*dot )  == __fmaf_rn(-2, dot, t)  (exact-equiv)
#pragma unroll
            for (int mf = 0; mf < 4; mf++)
#pragma unroll
                for (int h = 0; h < 2; h++) {
                    const int s = mf * 2 + h;
                    const float xsv = xs8[s];
                    float bv = best_v[s]; int bi = best_i[s];
#pragma unroll
                    for (int nf = 0; nf < 8; nf++) {
                        float v0 = __fmaf_rn(-2.f, acc[mf][nf][h * 2 + 0], __fadd_rn(xsv, e2f[nf].x));
                        float v1 = __fmaf_rn(-2.f, acc[mf][nf][h * 2 + 1], __fadd_rn(xsv, e2f[nf].y));
                        int k = k0 + wn * 64 + nf * 8 + 2 * (lane & 3);
                        if (v0 < bv) { bv = v0; bi = k; }
                        if (v1 < bv) { bv = v1; bi = k + 1; }
                    }
                    best_v[s] = bv; best_i[s] = bi;
                }
#pragma unroll
            for (int mf = 0; mf < 4; mf++)
#pragma unroll
                for (int nf = 0; nf < 8; nf++)
#pragma unroll
                    for (int r = 0; r < 4; r++) acc[mf][nf][r] = 0.f;
        }
    }

    // ---- cross-thread argmin reduction (16 owners per row, idx-aware) -----
    __syncthreads();
    float* rv   = (float*)smem;                 // 128*16 floats
    int*   ri   = (int*)(smem + 8192);          // 128*16 ints
    int*   sidx = (int*)(smem + 16384);         // 128 ints
    const int owner = wn * 4 + (lane & 3);
#pragma unroll
    for (int mf = 0; mf < 4; mf++)
#pragma unroll
        for (int h = 0; h < 2; h++) {
            int row = wm * 64 + mf * 16 + (lane >> 2) + 8 * h;
            rv[row * 16 + owner] = best_v[mf * 2 + h];
            ri[row * 16 + owner] = best_i[mf * 2 + h];
        }
    __syncthreads();
    if (tid < BM) {
        float bv = rv[tid * 16]; int bi = ri[tid * 16];
#pragma unroll
        for (int o = 1; o < 16; o++) {
            float v = rv[tid * 16 + o]; int ii = ri[tid * 16 + o];
            bool p = (v < bv) || (v == bv && ii < bi);
            bv = p ? v : bv; bi = p ? ii : bi;
        }
        sidx[tid] = bi;
        out[IDX_OFF + n0 + tid] = (float)bi;
    }
    __syncthreads();

    // ---- gather + straight-through out + loss partial ---------------------
    const int r  = tid & 127;
    const int dh = tid >> 7;
    const int er = sidx[r];
    const float* embrow = emb + (size_t)er * DD;
    const float* xr   = x + (size_t)b * (DD * 1024) + col0 + r;
    float*       outr = out + OUT_OFF + (size_t)b * (DD * 1024) + col0 + r;
    double lsum = 0.0;
#pragma unroll 4
    for (int dj = 0; dj < 128; dj++) {
        int d = dh * 128 + dj;
        float xp = xr[(size_t)d * 1024];
        float q  = embrow[d];
        float dl = __fsub_rn(q, xp);
        outr[(size_t)d * 1024] = __fadd_rn(xp, dl);
        lsum += (double)__fmul_rn(dl, dl);
    }

    __syncthreads();
    double* dr = (double*)(smem + 17408);
    dr[tid] = lsum;
    __syncthreads();
    for (int sft = 128; sft > 0; sft >>= 1) {
        if (tid < sft) dr[tid] += dr[tid + sft];
        __syncthreads();
    }
    if (tid == 0) g_part[blockIdx.x] = dr[0];
}

// ---------------------------------------------------------------------------
// finalize loss
// ---------------------------------------------------------------------------
__global__ void vq_final(float* __restrict__ out) {
    if (blockIdx.x == 0 && threadIdx.x == 0) {
        double s = 0.0;
        for (int i = 0; i < NCTA; i++) s += g_part[i];
        float L = (float)(s / (double)((size_t)NN * DD));
        out[LOSS_OFF] = __fadd_rn(L, __fmul_rn(0.25f, L));
    }
}

extern "C" void kernel_launch(void* const* d_in, const int* in_sizes, int n_in,
                              void* d_out, int out_size) {
    const float* x   = (const float*)d_in[0];
    const float* emb = (const float*)d_in[1];
    float* out = (float*)d_out;

    cudaFuncSetAttribute(vq_main, cudaFuncAttributeMaxDynamicSharedMemorySize, SMEM_DYN);

    vq_e2     <<<KK * 32 / 256, 256>>>(emb);
    vq_xs     <<<NN / 256,      256>>>(x);
    vq_split_x<<<1024,          256>>>(x);
    vq_split_e<<<KK / 8,        256>>>(emb);
    vq_main   <<<NCTA, 256, SMEM_DYN>>>(x, emb, out);
    vq_final  <<<1, 32>>>(out);
}

// round 7
// speedup vs baseline: 1.9039x; 1.3987x over previous
#include <cuda_runtime.h>
#include <cuda_bf16.h>
#include <cstdint>

// -------------------------- problem constants ------------------------------
#define NN 32768        // rows (B*H*W)
#define DD 256          // embedding dim
#define KK 8192         // codebook size
#define BM 128          // rows per CTA
#define BN 256          // codes per n-tile
#define NTILES (KK / BN)            // 32
#define SPT 16                      // stages per tile: 8 tf32 + 8 bf16
#define NSTG (NTILES * SPT)         // 512 stages
#define NCTA (NN / BM)              // 256

#define OUT_OFF  0
#define LOSS_OFF 8388608
#define IDX_OFF  8388609

#define STG_BYTES 49152   // A 16 KB + B 32 KB  (128 B per row in ALL stage types)
#define B_OFF     16384
#define SMEM_DYN  (4 * STG_BYTES)   // 196608

__device__ float  g_e2[KK];
__device__ float  g_xs[NN];
__device__ double g_part[NCTA];

// tf32 hi operands, chunk-major [chunk 0..7][row][32 floats] (128 B/row)
__device__ __align__(16) float g_At[(size_t)8 * NN * 32];   // 33.5 MB
__device__ __align__(16) float g_Et[(size_t)8 * KK * 32];   // 8.4 MB
// bf16 correction operands, chunk-major [chunk 0..7][row][64 bf16] (128 B/row)
// A: chunks 0-3 = bf16(xhi) d0..255, chunks 4-7 = bf16(xlo)
// E: chunks 0-3 = bf16(elo),         chunks 4-7 = bf16(ehi)
__device__ __align__(16) __nv_bfloat16 g_Ab[(size_t)8 * NN * 64];  // 33.5 MB
__device__ __align__(16) __nv_bfloat16 g_Eb[(size_t)8 * KK * 64];  // 8.4 MB

// ---------------------------- asm helpers ----------------------------------
__device__ __forceinline__ uint32_t smem_u32(const void* p) {
    uint32_t a;
    asm("{ .reg .u64 t; cvta.to.shared.u64 t, %1; cvt.u32.u64 %0, t; }" : "=r"(a) : "l"(p));
    return a;
}
__device__ __forceinline__ float to_tf32(float a) {
    uint32_t r;
    asm("cvt.rna.tf32.f32 %0, %1;" : "=r"(r) : "f"(a));
    return __uint_as_float(r);
}
#define CPA(dst, src) asm volatile("cp.async.cg.shared.global [%0], [%1], 16;" :: "r"(dst), "l"(src))
#define CPC()         asm volatile("cp.async.commit_group;" ::: "memory")
#define CPW(n)        asm volatile("cp.async.wait_group %0;" :: "n"(n) : "memory")

__device__ __forceinline__ void ldsm4(uint32_t* r, uint32_t addr) {
    asm volatile("ldmatrix.sync.aligned.m8n8.x4.shared.b16 {%0,%1,%2,%3}, [%4];"
        : "=r"(r[0]), "=r"(r[1]), "=r"(r[2]), "=r"(r[3]) : "r"(addr));
}
__device__ __forceinline__ void mma_tf32(float* c, const uint32_t* a, const uint32_t* b) {
    asm volatile("mma.sync.aligned.m16n8k8.row.col.f32.tf32.tf32.f32 "
        "{%0,%1,%2,%3}, {%4,%5,%6,%7}, {%8,%9}, {%0,%1,%2,%3};"
        : "+f"(c[0]), "+f"(c[1]), "+f"(c[2]), "+f"(c[3])
        : "r"(a[0]), "r"(a[1]), "r"(a[2]), "r"(a[3]), "r"(b[0]), "r"(b[1]));
}
__device__ __forceinline__ void mma_bf16(float* c, const uint32_t* a, const uint32_t* b) {
    asm volatile("mma.sync.aligned.m16n8k16.row.col.f32.bf16.bf16.f32 "
        "{%0,%1,%2,%3}, {%4,%5,%6,%7}, {%8,%9}, {%0,%1,%2,%3};"
        : "+f"(c[0]), "+f"(c[1]), "+f"(c[2]), "+f"(c[3])
        : "r"(a[0]), "r"(a[1]), "r"(a[2]), "r"(a[3]), "r"(b[0]), "r"(b[1]));
}

// ---------------------------------------------------------------------------
// prep kernels
// ---------------------------------------------------------------------------
__global__ void vq_e2(const float* __restrict__ emb) {
    int gw = (blockIdx.x * blockDim.x + threadIdx.x) >> 5;
    int l  = threadIdx.x & 31;
    if (gw >= KK) return;
    const float* e = emb + (size_t)gw * DD;
    float s = 0.f;
#pragma unroll
    for (int t = 0; t < DD / 32; t++) { float v = e[l + 32 * t]; s = fmaf(v, v, s); }
#pragma unroll
    for (int o = 16; o > 0; o >>= 1) s += __shfl_xor_sync(0xffffffffu, s, o);
    if (l == 0) g_e2[gw] = s;
}

__global__ void vq_xs(const float* __restrict__ x) {
    int n = blockIdx.x * blockDim.x + threadIdx.x;
    if (n >= NN) return;
    int b = n >> 10, c = n & 1023;
    const float* xb = x + (size_t)b * (DD * 1024) + c;
    float s = 0.f;
#pragma unroll 8
    for (int d = 0; d < DD; d++) { float v = xb[(size_t)d * 1024]; s = fmaf(v, v, s); }
    g_xs[n] = s;
}

// x split: grid 1024 = 8 d-chunks x 128 row-blocks(256); smem transpose
__global__ void vq_split_x(const float* __restrict__ x) {
    __shared__ float sx[32][257];
    const int t  = threadIdx.x;
    const int dc = blockIdx.x & 7;
    const int nb = blockIdx.x >> 3;
    const int n0 = nb * 256;
    const int b  = n0 >> 10, hw0 = n0 & 1023;
    const float* xb = x + (size_t)b * (DD * 1024) + (size_t)(dc * 32) * 1024 + hw0;
#pragma unroll
    for (int dd = 0; dd < 32; dd++) sx[dd][t] = xb[(size_t)dd * 1024 + t];
    __syncthreads();

    float hi[32], lo[32];
#pragma unroll
    for (int d = 0; d < 32; d++) {
        float v = sx[d][t];
        hi[d] = to_tf32(v);
        lo[d] = __fsub_rn(v, hi[d]);   // exact (Sterbenz)
    }
    // tf32 hi chunk
    float* dh = g_At + ((size_t)dc * NN + n0 + t) * 32;
#pragma unroll
    for (int q = 0; q < 8; q++)
        *(float4*)(dh + 4 * q) = make_float4(hi[4 * q], hi[4 * q + 1], hi[4 * q + 2], hi[4 * q + 3]);
    // bf16 chunks: xhi -> chunk dc>>1 at half (dc&1), xlo -> chunk 4+(dc>>1)
    uint32_t ph[16], pl[16];
#pragma unroll
    for (int u = 0; u < 16; u++) {
        uint32_t h0 = __bfloat16_as_ushort(__float2bfloat16_rn(hi[2 * u]));
        uint32_t h1 = __bfloat16_as_ushort(__float2bfloat16_rn(hi[2 * u + 1]));
        ph[u] = h0 | (h1 << 16);
        uint32_t l0 = __bfloat16_as_ushort(__float2bfloat16_rn(lo[2 * u]));
        uint32_t l1 = __bfloat16_as_ushort(__float2bfloat16_rn(lo[2 * u + 1]));
        pl[u] = l0 | (l1 << 16);
    }
    __nv_bfloat16* bh = g_Ab + ((size_t)(dc >> 1) * NN + n0 + t) * 64 + (dc & 1) * 32;
    __nv_bfloat16* bl = g_Ab + ((size_t)(4 + (dc >> 1)) * NN + n0 + t) * 64 + (dc & 1) * 32;
#pragma unroll
    for (int p = 0; p < 4; p++) {
        *(uint4*)(bh + 8 * p) = make_uint4(ph[4 * p], ph[4 * p + 1], ph[4 * p + 2], ph[4 * p + 3]);
        *(uint4*)(bl + 8 * p) = make_uint4(pl[4 * p], pl[4 * p + 1], pl[4 * p + 2], pl[4 * p + 3]);
    }
}

// emb split: 1 warp per code row
__global__ void vq_split_e(const float* __restrict__ emb) {
    int wid = threadIdx.x >> 5, lane = threadIdx.x & 31;
    int k = blockIdx.x * 8 + wid;
    const float* er = emb + (size_t)k * DD;
#pragma unroll
    for (int dc = 0; dc < 8; dc++) {
        float v  = er[dc * 32 + lane];
        float hi = to_tf32(v);
        float lo = __fsub_rn(v, hi);    // exact
        g_Et[((size_t)dc * KK + k) * 32 + lane] = hi;
        // elo -> chunk dc>>1, ehi -> chunk 4+(dc>>1)
        g_Eb[((size_t)(dc >> 1) * KK + k) * 64 + (dc & 1) * 32 + lane] = __float2bfloat16_rn(lo);
        g_Eb[((size_t)(4 + (dc >> 1)) * KK + k) * 64 + (dc & 1) * 32 + lane] = __float2bfloat16_rn(hi);
    }
}

// ---------------------------------------------------------------------------
// pipeline: issue one stage (A 16 KB + B 32 KB, XOR-swizzled 16B granules)
// stage c in [0,8): tf32 hi.hi;  c in [8,16): bf16 corrections (chunk c-8)
// ---------------------------------------------------------------------------
__device__ __forceinline__ void issue(uint32_t sb, int slot, int g, int rt, int tid) {
    const int ti = g >> 4, c = g & 15;
    const char* aSrc;
    const char* bSrc;
    if (c < 8) {
        aSrc = (const char*)g_At + ((size_t)c * NN + (size_t)rt * BM) * 128;
        bSrc = (const char*)g_Et + ((size_t)c * KK + (size_t)ti * BN) * 128;
    } else {
        const int cc = c - 8;
        aSrc = (const char*)g_Ab + ((size_t)cc * NN + (size_t)rt * BM) * 128;
        bSrc = (const char*)g_Eb + ((size_t)cc * KK + (size_t)ti * BN) * 128;
    }
    const uint32_t aDst = sb + slot * STG_BYTES;
    const uint32_t bDst = aDst + B_OFF;
#pragma unroll
    for (int p = 0; p < 4; p++) {
        int i = tid + p * 256, row = i >> 3, gg = i & 7;
        CPA(aDst + row * 128 + ((gg ^ (row & 7)) << 4), aSrc + (size_t)i * 16);
    }
#pragma unroll
    for (int p = 0; p < 8; p++) {
        int i = tid + p * 256, row = i >> 3, gg = i & 7;
        CPA(bDst + row * 128 + ((gg ^ (row & 7)) << 4), bSrc + (size_t)i * 16);
    }
}

// consume one stage: 4 k-steps of (12 ldmatrix.x4 + 32 mma)
// identical addressing for tf32 (2 granules = k8) and bf16 (2 granules = k16)
template <int BF>
__device__ __forceinline__ void consume(uint32_t aS, uint32_t bS, int wm, int wn,
                                        int lane, float (&acc)[4][8][4]) {
    const int grp = lane >> 3;
#pragma unroll
    for (int ks = 0; ks < 4; ks++) {
        uint32_t a[4][4];
#pragma unroll
        for (int mf = 0; mf < 4; mf++) {
            int row = wm * 64 + mf * 16 + (lane & 7) + (grp & 1) * 8;
            int gg  = 2 * ks + (grp >> 1);
            ldsm4(a[mf], aS + row * 128 + ((gg ^ (row & 7)) << 4));
        }
        uint32_t bfr[8][2];
#pragma unroll
        for (int nf2 = 0; nf2 < 4; nf2++) {
            int row = wn * 64 + nf2 * 16 + (lane & 7) + (grp >> 1) * 8;
            int gg  = 2 * ks + (grp & 1);
            uint32_t r[4];
            ldsm4(r, bS + row * 128 + ((gg ^ (row & 7)) << 4));
            bfr[2 * nf2][0] = r[0]; bfr[2 * nf2][1] = r[1];
            bfr[2 * nf2 + 1][0] = r[2]; bfr[2 * nf2 + 1][1] = r[3];
        }
#pragma unroll
        for (int mf = 0; mf < 4; mf++)
#pragma unroll
            for (int nf = 0; nf < 8; nf++) {
                if (BF) mma_bf16(acc[mf][nf], a[mf], bfr[nf]);
                else    mma_tf32(acc[mf][nf], a[mf], bfr[nf]);
            }
    }
}

// ---------------------------------------------------------------------------
// main fused kernel
// ---------------------------------------------------------------------------
__global__ void __launch_bounds__(256)
vq_main(const float* __restrict__ x, const float* __restrict__ emb,
        float* __restrict__ out)
{
    extern __shared__ __align__(16) char smem[];
    const uint32_t sb = smem_u32(smem);
    const int tid = threadIdx.x, lane = tid & 31, wid = tid >> 5;
    const int wm = wid & 1, wn = wid >> 1;            // 2m x 4n warps
    const int rt = blockIdx.x;
    const int n0 = rt * BM, b = n0 >> 10, col0 = n0 & 1023;

    float xs8[8];
#pragma unroll
    for (int mf = 0; mf < 4; mf++)
#pragma unroll
        for (int h = 0; h < 2; h++)
            xs8[mf * 2 + h] = g_xs[n0 + wm * 64 + mf * 16 + (lane >> 2) + 8 * h];

    float acc[4][8][4];
#pragma unroll
    for (int mf = 0; mf < 4; mf++)
#pragma unroll
        for (int nf = 0; nf < 8; nf++)
#pragma unroll
            for (int r = 0; r < 4; r++) acc[mf][nf][r] = 0.f;

    float best_v[8]; int best_i[8];
#pragma unroll
    for (int s = 0; s < 8; s++) { best_v[s] = __int_as_float(0x7f800000); best_i[s] = 0; }

    float2 e2f[8];

    issue(sb, 0, 0, rt, tid); CPC();
    issue(sb, 1, 1, rt, tid); CPC();
    issue(sb, 2, 2, rt, tid); CPC();

#pragma unroll 1
    for (int g = 0; g < NSTG; g++) {
        CPW(2);
        __syncthreads();
        if (g + 3 < NSTG) issue(sb, (g + 3) & 3, g + 3, rt, tid);
        CPC();

        const int ti = g >> 4, c = g & 15;
        const int k0 = ti * BN;
        if (c == 0) {
#pragma unroll
            for (int nf = 0; nf < 8; nf++)
                e2f[nf] = *(const float2*)&g_e2[k0 + wn * 64 + nf * 8 + 2 * (lane & 3)];
        }

        const uint32_t aS = sb + (g & 3) * STG_BYTES;
        if (c < 8) consume<0>(aS, aS + B_OFF, wm, wn, lane, acc);
        else       consume<1>(aS, aS + B_OFF, wm, wn, lane, acc);

        if (c == SPT - 1) {
            // dist = fl( fl(xs+e2) - 2*dot )  == __fmaf_rn(-2, dot, t)  (exact-equiv)
#pragma unroll
            for (int mf = 0; mf < 4; mf++)
#pragma unroll
                for (int h = 0; h < 2; h++) {
                    const int s = mf * 2 + h;
                    const float xsv = xs8[s];
                    float bv = best_v[s]; int bi = best_i[s];
#pragma unroll
                    for (int nf = 0; nf < 8; nf++) {
                        float v0 = __fmaf_rn(-2.f, acc[mf][nf][h * 2 + 0], __fadd_rn(xsv, e2f[nf].x));
                        float v1 = __fmaf_rn(-2.f, acc[mf][nf][h * 2 + 1], __fadd_rn(xsv, e2f[nf].y));
                        int k = k0 + wn * 64 + nf * 8 + 2 * (lane & 3);
                        if (v0 < bv) { bv = v0; bi = k; }
                        if (v1 < bv) { bv = v1; bi = k + 1; }
                    }
                    best_v[s] = bv; best_i[s] = bi;
                }
#pragma unroll
            for (int mf = 0; mf < 4; mf++)
#pragma unroll
                for (int nf = 0; nf < 8; nf++)
#pragma unroll
                    for (int r = 0; r < 4; r++) acc[mf][nf][r] = 0.f;
        }
    }

    // ---- cross-thread argmin reduction (16 owners per row, idx-aware) -----
    __syncthreads();
    float* rv   = (float*)smem;                 // 128*16 floats
    int*   ri   = (int*)(smem + 8192);          // 128*16 ints
    int*   sidx = (int*)(smem + 16384);         // 128 ints
    const int owner = wn * 4 + (lane & 3);
#pragma unroll
    for (int mf = 0; mf < 4; mf++)
#pragma unroll
        for (int h = 0; h < 2; h++) {
            int row = wm * 64 + mf * 16 + (lane >> 2) + 8 * h;
            rv[row * 16 + owner] = best_v[mf * 2 + h];
            ri[row * 16 + owner] = best_i[mf * 2 + h];
        }
    __syncthreads();
    if (tid < BM) {
        float bv = rv[tid * 16]; int bi = ri[tid * 16];
#pragma unroll
        for (int o = 1; o < 16; o++) {
            float v = rv[tid * 16 + o]; int ii = ri[tid * 16 + o];
            bool p = (v < bv) || (v == bv && ii < bi);
            bv = p ? v : bv; bi = p ? ii : bi;
        }
        sidx[tid] = bi;
        out[IDX_OFF + n0 + tid] = (float)bi;
    }
    __syncthreads();

    // ---- gather + straight-through out + loss partial ---------------------
    const int r  = tid & 127;
    const int dh = tid >> 7;
    const int er = sidx[r];
    const float* embrow = emb + (size_t)er * DD;
    const float* xr   = x + (size_t)b * (DD * 1024) + col0 + r;
    float*       outr = out + OUT_OFF + (size_t)b * (DD * 1024) + col0 + r;
    double lsum = 0.0;
#pragma unroll 4
    for (int dj = 0; dj < 128; dj++) {
        int d = dh * 128 + dj;
        float xp = xr[(size_t)d * 1024];
        float q  = embrow[d];
        float dl = __fsub_rn(q, xp);
        outr[(size_t)d * 1024] = __fadd_rn(xp, dl);
        lsum += (double)__fmul_rn(dl, dl);
    }

    __syncthreads();
    double* dr = (double*)(smem + 17408);
    dr[tid] = lsum;
    __syncthreads();
    for (int sft = 128; sft > 0; sft >>= 1) {
        if (tid < sft) dr[tid] += dr[tid + sft];
        __syncthreads();
    }
    if (tid == 0) g_part[blockIdx.x] = dr[0];
}

// ---------------------------------------------------------------------------
// finalize loss
// ---------------------------------------------------------------------------
__global__ void vq_final(float* __restrict__ out) {
    if (blockIdx.x == 0 && threadIdx.x == 0) {
        double s = 0.0;
        for (int i = 0; i < NCTA; i++) s += g_part[i];
        float L = (float)(s / (double)((size_t)NN * DD));
        out[LOSS_OFF] = __fadd_rn(L, __fmul_rn(0.25f, L));
    }
}

extern "C" void kernel_launch(void* const* d_in, const int* in_sizes, int n_in,
                              void* d_out, int out_size) {
    const float* x   = (const float*)d_in[0];
    const float* emb = (const float*)d_in[1];
    float* out = (float*)d_out;

    cudaFuncSetAttribute(vq_main, cudaFuncAttributeMaxDynamicSharedMemorySize, SMEM_DYN);

    vq_e2     <<<KK * 32 / 256, 256>>>(emb);
    vq_xs     <<<NN / 256,      256>>>(x);
    vq_split_x<<<1024,          256>>>(x);
    vq_split_e<<<KK / 8,        256>>>(emb);
    vq_main   <<<NCTA, 256, SMEM_DYN>>>(x, emb, out);
    vq_final  <<<1, 32>>>(out);
}

// round 8
// speedup vs baseline: 2.6258x; 1.3792x over previous
#include <cuda_runtime.h>
#include <cuda_fp16.h>
#include <cstdint>

// -------------------------- problem constants ------------------------------
#define NN 32768        // rows (B*H*W)
#define DD 256          // embedding dim
#define KK 8192         // codebook size
#define BM 128          // rows per CTA
#define BN 256          // codes per n-tile
#define NTILES (KK / BN)            // 32
#define SPT 12                      // stages/tile: 4 h1c1 + 4 h1c2 + 4 h2c1
#define NSTG (NTILES * SPT)         // 384 stages
#define NCTA (NN / BM)              // 256

#define OUT_OFF  0
#define LOSS_OFF 8388608
#define IDX_OFF  8388609

#define STG_BYTES 49152   // A 16 KB + B 32 KB (128 B per row)
#define B_OFF     16384
#define SMEM_DYN  (4 * STG_BYTES)   // 196608

#define ESCALE 65536.0f             // e pre-scale 2^16 (exact)

__device__ float  g_e2[KK];
__device__ float  g_xs[NN];
__device__ double g_part[NCTA];

// fp16 operands, chunk-major [chunk][row][64 halves] (128 B/row)
// A: chunks 0-3 = h1 = fp16(x) (d 0..255), chunks 4-7 = h2 = fp16(x - h1)
// E: chunks 0-3 = c1 = fp16(e*2^16),       chunks 4-7 = c2 = fp16(e*2^16 - c1)
__device__ __align__(16) __half g_Ah[(size_t)8 * NN * 64];  // 33.5 MB
__device__ __align__(16) __half g_Eh[(size_t)8 * KK * 64];  // 8.4 MB

// ---------------------------- asm helpers ----------------------------------
__device__ __forceinline__ uint32_t smem_u32(const void* p) {
    uint32_t a;
    asm("{ .reg .u64 t; cvta.to.shared.u64 t, %1; cvt.u32.u64 %0, t; }" : "=r"(a) : "l"(p));
    return a;
}
#define CPA(dst, src) asm volatile("cp.async.cg.shared.global [%0], [%1], 16;" :: "r"(dst), "l"(src))
#define CPC()         asm volatile("cp.async.commit_group;" ::: "memory")
#define CPW(n)        asm volatile("cp.async.wait_group %0;" :: "n"(n) : "memory")

__device__ __forceinline__ void ldsm4(uint32_t* r, uint32_t addr) {
    asm volatile("ldmatrix.sync.aligned.m8n8.x4.shared.b16 {%0,%1,%2,%3}, [%4];"
        : "=r"(r[0]), "=r"(r[1]), "=r"(r[2]), "=r"(r[3]) : "r"(addr));
}
__device__ __forceinline__ void mma_fp16(float* c, const uint32_t* a, const uint32_t* b) {
    asm volatile("mma.sync.aligned.m16n8k16.row.col.f32.f16.f16.f32 "
        "{%0,%1,%2,%3}, {%4,%5,%6,%7}, {%8,%9}, {%0,%1,%2,%3};"
        : "+f"(c[0]), "+f"(c[1]), "+f"(c[2]), "+f"(c[3])
        : "r"(a[0]), "r"(a[1]), "r"(a[2]), "r"(a[3]), "r"(b[0]), "r"(b[1]));
}

// ---------------------------------------------------------------------------
// prep kernels
// ---------------------------------------------------------------------------
__global__ void vq_e2(const float* __restrict__ emb) {
    int gw = (blockIdx.x * blockDim.x + threadIdx.x) >> 5;
    int l  = threadIdx.x & 31;
    if (gw >= KK) return;
    const float* e = emb + (size_t)gw * DD;
    float s = 0.f;
#pragma unroll
    for (int t = 0; t < DD / 32; t++) { float v = e[l + 32 * t]; s = fmaf(v, v, s); }
#pragma unroll
    for (int o = 16; o > 0; o >>= 1) s += __shfl_xor_sync(0xffffffffu, s, o);
    if (l == 0) g_e2[gw] = s;
}

__global__ void vq_xs(const float* __restrict__ x) {
    int n = blockIdx.x * blockDim.x + threadIdx.x;
    if (n >= NN) return;
    int b = n >> 10, c = n & 1023;
    const float* xb = x + (size_t)b * (DD * 1024) + c;
    float s = 0.f;
#pragma unroll 8
    for (int d = 0; d < DD; d++) { float v = xb[(size_t)d * 1024]; s = fmaf(v, v, s); }
    g_xs[n] = s;
}

// x split: grid 1024 = 8 d-slices(32) x 128 row-blocks(256); smem transpose
__global__ void vq_split_x(const float* __restrict__ x) {
    __shared__ float sx[32][257];
    const int t  = threadIdx.x;
    const int dc = blockIdx.x & 7;
    const int nb = blockIdx.x >> 3;
    const int n0 = nb * 256;
    const int b  = n0 >> 10, hw0 = n0 & 1023;
    const float* xb = x + (size_t)b * (DD * 1024) + (size_t)(dc * 32) * 1024 + hw0;
#pragma unroll
    for (int dd = 0; dd < 32; dd++) sx[dd][t] = xb[(size_t)dd * 1024 + t];
    __syncthreads();

    uint32_t p1[16], p2[16];
#pragma unroll
    for (int u = 0; u < 16; u++) {
        float v0 = sx[2 * u][t], v1 = sx[2 * u + 1][t];
        __half a0 = __float2half_rn(v0);
        __half a1 = __float2half_rn(v1);
        __half b0 = __float2half_rn(__fsub_rn(v0, __half2float(a0)));  // residual exact
        __half b1 = __float2half_rn(__fsub_rn(v1, __half2float(a1)));
        p1[u] = (uint32_t)__half_as_ushort(a0) | ((uint32_t)__half_as_ushort(a1) << 16);
        p2[u] = (uint32_t)__half_as_ushort(b0) | ((uint32_t)__half_as_ushort(b1) << 16);
    }
    __half* d1 = g_Ah + ((size_t)(dc >> 1) * NN + n0 + t) * 64 + (dc & 1) * 32;
    __half* d2 = g_Ah + ((size_t)(4 + (dc >> 1)) * NN + n0 + t) * 64 + (dc & 1) * 32;
#pragma unroll
    for (int p = 0; p < 4; p++) {
        *(uint4*)(d1 + 8 * p) = make_uint4(p1[4 * p], p1[4 * p + 1], p1[4 * p + 2], p1[4 * p + 3]);
        *(uint4*)(d2 + 8 * p) = make_uint4(p2[4 * p], p2[4 * p + 1], p2[4 * p + 2], p2[4 * p + 3]);
    }
}

// emb split: 1 warp per code row; e scaled by 2^16 (exact)
__global__ void vq_split_e(const float* __restrict__ emb) {
    int wid = threadIdx.x >> 5, lane = threadIdx.x & 31;
    int k = blockIdx.x * 8 + wid;
    const float* er = emb + (size_t)k * DD;
#pragma unroll
    for (int dc = 0; dc < 8; dc++) {
        float es = __fmul_rn(er[dc * 32 + lane], ESCALE);  // exact scaling
        __half c1 = __float2half_rn(es);
        __half c2 = __float2half_rn(__fsub_rn(es, __half2float(c1)));  // residual exact
        g_Eh[((size_t)(dc >> 1) * KK + k) * 64 + (dc & 1) * 32 + lane] = c1;
        g_Eh[((size_t)(4 + (dc >> 1)) * KK + k) * 64 + (dc & 1) * 32 + lane] = c2;
    }
}

// ---------------------------------------------------------------------------
// pipeline: issue one stage (A 16 KB + B 32 KB, XOR-swizzled 16B granules)
// stage c in [0,4): h1*c1; [4,8): h1*c2; [8,12): h2*c1
// ---------------------------------------------------------------------------
__device__ __forceinline__ void issue(uint32_t sb, int slot, int g, int rt, int tid) {
    const int ti = g / SPT, c = g - ti * SPT;
    const int ac = (c < 8) ? (c & 3) : (c - 4);   // 0-3 / 0-3 / 4-7
    const int bc = (c < 8) ? c : (c - 8);          // 0-3 / 4-7 / 0-3
    const char* aSrc = (const char*)g_Ah + ((size_t)ac * NN + (size_t)rt * BM) * 128;
    const char* bSrc = (const char*)g_Eh + ((size_t)bc * KK + (size_t)ti * BN) * 128;
    const uint32_t aDst = sb + slot * STG_BYTES;
    const uint32_t bDst = aDst + B_OFF;
#pragma unroll
    for (int p = 0; p < 4; p++) {
        int i = tid + p * 256, row = i >> 3, gg = i & 7;
        CPA(aDst + row * 128 + ((gg ^ (row & 7)) << 4), aSrc + (size_t)i * 16);
    }
#pragma unroll
    for (int p = 0; p < 8; p++) {
        int i = tid + p * 256, row = i >> 3, gg = i & 7;
        CPA(bDst + row * 128 + ((gg ^ (row & 7)) << 4), bSrc + (size_t)i * 16);
    }
}

// consume one stage: 4 k-steps of (12 ldmatrix.x4 + 32 mma), k16 fp16
__device__ __forceinline__ void consume(uint32_t aS, uint32_t bS, int wm, int wn,
                                        int lane, float (&acc)[4][8][4]) {
    const int grp = lane >> 3;
#pragma unroll
    for (int ks = 0; ks < 4; ks++) {
        uint32_t a[4][4];
#pragma unroll
        for (int mf = 0; mf < 4; mf++) {
            int row = wm * 64 + mf * 16 + (lane & 7) + (grp & 1) * 8;
            int gg  = 2 * ks + (grp >> 1);
            ldsm4(a[mf], aS + row * 128 + ((gg ^ (row & 7)) << 4));
        }
        uint32_t bfr[8][2];
#pragma unroll
        for (int nf2 = 0; nf2 < 4; nf2++) {
            int row = wn * 64 + nf2 * 16 + (lane & 7) + (grp >> 1) * 8;
            int gg  = 2 * ks + (grp & 1);
            uint32_t r[4];
            ldsm4(r, bS + row * 128 + ((gg ^ (row & 7)) << 4));
            bfr[2 * nf2][0] = r[0]; bfr[2 * nf2][1] = r[1];
            bfr[2 * nf2 + 1][0] = r[2]; bfr[2 * nf2 + 1][1] = r[3];
        }
#pragma unroll
        for (int mf = 0; mf < 4; mf++)
#pragma unroll
            for (int nf = 0; nf < 8; nf++)
                mma_fp16(acc[mf][nf], a[mf], bfr[nf]);
    }
}

// ---------------------------------------------------------------------------
// main fused kernel
// ---------------------------------------------------------------------------
__global__ void __launch_bounds__(256)
vq_main(const float* __restrict__ x, const float* __restrict__ emb,
        float* __restrict__ out)
{
    extern __shared__ __align__(16) char smem[];
    const uint32_t sb = smem_u32(smem);
    const int tid = threadIdx.x, lane = tid & 31, wid = tid >> 5;
    const int wm = wid & 1, wn = wid >> 1;            // 2m x 4n warps
    const int rt = blockIdx.x;
    const int n0 = rt * BM, b = n0 >> 10, col0 = n0 & 1023;

    float xs8[8];
#pragma unroll
    for (int mf = 0; mf < 4; mf++)
#pragma unroll
        for (int h = 0; h < 2; h++)
            xs8[mf * 2 + h] = g_xs[n0 + wm * 64 + mf * 16 + (lane >> 2) + 8 * h];

    float acc[4][8][4];
#pragma unroll
    for (int mf = 0; mf < 4; mf++)
#pragma unroll
        for (int nf = 0; nf < 8; nf++)
#pragma unroll
            for (int r = 0; r < 4; r++) acc[mf][nf][r] = 0.f;

    float best_v[8]; int best_i[8];
#pragma unroll
    for (int s = 0; s < 8; s++) { best_v[s] = __int_as_float(0x7f800000); best_i[s] = 0; }

    float2 e2f[8];

    issue(sb, 0, 0, rt, tid); CPC();
    issue(sb, 1, 1, rt, tid); CPC();
    issue(sb, 2, 2, rt, tid); CPC();

#pragma unroll 1
    for (int g = 0; g < NSTG; g++) {
        CPW(2);
        __syncthreads();
        if (g + 3 < NSTG) issue(sb, (g + 3) & 3, g + 3, rt, tid);
        CPC();

        const int ti = g / SPT, c = g - ti * SPT;
        const int k0 = ti * BN;
        if (c == 0) {
#pragma unroll
            for (int nf = 0; nf < 8; nf++)
                e2f[nf] = *(const float2*)&g_e2[k0 + wn * 64 + nf * 8 + 2 * (lane & 3)];
        }

        const uint32_t aS = sb + (g & 3) * STG_BYTES;
        consume(aS, aS + B_OFF, wm, wn, lane, acc);

        if (c == SPT - 1) {
            // acc = dot * 2^16;  dist = fl( fl(xs+e2) - 2*dot ) == fmaf(-2^-15, acc, t)
#pragma unroll
            for (int mf = 0; mf < 4; mf++)
#pragma unroll
                for (int h = 0; h < 2; h++) {
                    const int s = mf * 2 + h;
                    const float xsv = xs8[s];
                    float bv = best_v[s]; int bi = best_i[s];
#pragma unroll
                    for (int nf = 0; nf < 8; nf++) {
                        float v0 = __fmaf_rn(-0x1p-15f, acc[mf][nf][h * 2 + 0], __fadd_rn(xsv, e2f[nf].x));
                        float v1 = __fmaf_rn(-0x1p-15f, acc[mf][nf][h * 2 + 1], __fadd_rn(xsv, e2f[nf].y));
                        int k = k0 + wn * 64 + nf * 8 + 2 * (lane & 3);
                        if (v0 < bv) { bv = v0; bi = k; }
                        if (v1 < bv) { bv = v1; bi = k + 1; }
                    }
                    best_v[s] = bv; best_i[s] = bi;
                }
#pragma unroll
            for (int mf = 0; mf < 4; mf++)
#pragma unroll
                for (int nf = 0; nf < 8; nf++)
#pragma unroll
                    for (int r = 0; r < 4; r++) acc[mf][nf][r] = 0.f;
        }
    }

    // ---- cross-thread argmin reduction (16 owners per row, idx-aware) -----
    __syncthreads();
    float* rv   = (float*)smem;                 // 128*16 floats
    int*   ri   = (int*)(smem + 8192);          // 128*16 ints
    int*   sidx = (int*)(smem + 16384);         // 128 ints
    const int owner = wn * 4 + (lane & 3);
#pragma unroll
    for (int mf = 0; mf < 4; mf++)
#pragma unroll
        for (int h = 0; h < 2; h++) {
            int row = wm * 64 + mf * 16 + (lane >> 2) + 8 * h;
            rv[row * 16 + owner] = best_v[mf * 2 + h];
            ri[row * 16 + owner] = best_i[mf * 2 + h];
        }
    __syncthreads();
    if (tid < BM) {
        float bv = rv[tid * 16]; int bi = ri[tid * 16];
#pragma unroll
        for (int o = 1; o < 16; o++) {
            float v = rv[tid * 16 + o]; int ii = ri[tid * 16 + o];
            bool p = (v < bv) || (v == bv && ii < bi);
            bv = p ? v : bv; bi = p ? ii : bi;
        }
        sidx[tid] = bi;
        out[IDX_OFF + n0 + tid] = (float)bi;
    }
    __syncthreads();

    // ---- gather + straight-through out + loss partial ---------------------
    const int r  = tid & 127;
    const int dh = tid >> 7;
    const int er = sidx[r];
    const float* embrow = emb + (size_t)er * DD;
    const float* xr   = x + (size_t)b * (DD * 1024) + col0 + r;
    float*       outr = out + OUT_OFF + (size_t)b * (DD * 1024) + col0 + r;
    double lsum = 0.0;
#pragma unroll 4
    for (int dj = 0; dj < 128; dj++) {
        int d = dh * 128 + dj;
        float xp = xr[(size_t)d * 1024];
        float q  = embrow[d];
        float dl = __fsub_rn(q, xp);
        outr[(size_t)d * 1024] = __fadd_rn(xp, dl);
        lsum += (double)__fmul_rn(dl, dl);
    }

    __syncthreads();
    double* dr = (double*)(smem + 17408);
    dr[tid] = lsum;
    __syncthreads();
    for (int sft = 128; sft > 0; sft >>= 1) {
        if (tid < sft) dr[tid] += dr[tid + sft];
        __syncthreads();
    }
    if (tid == 0) g_part[blockIdx.x] = dr[0];
}

// ---------------------------------------------------------------------------
// finalize loss
// ---------------------------------------------------------------------------
__global__ void vq_final(float* __restrict__ out) {
    if (blockIdx.x == 0 && threadIdx.x == 0) {
        double s = 0.0;
        for (int i = 0; i < NCTA; i++) s += g_part[i];
        float L = (float)(s / (double)((size_t)NN * DD));
        out[LOSS_OFF] = __fadd_rn(L, __fmul_rn(0.25f, L));
    }
}

extern "C" void kernel_launch(void* const* d_in, const int* in_sizes, int n_in,
                              void* d_out, int out_size) {
    const float* x   = (const float*)d_in[0];
    const float* emb = (const float*)d_in[1];
    float* out = (float*)d_out;

    cudaFuncSetAttribute(vq_main, cudaFuncAttributeMaxDynamicSharedMemorySize, SMEM_DYN);

    vq_e2     <<<KK * 32 / 256, 256>>>(emb);
    vq_xs     <<<NN / 256,      256>>>(x);
    vq_split_x<<<1024,          256>>>(x);
    vq_split_e<<<KK / 8,        256>>>(emb);
    vq_main   <<<NCTA, 256, SMEM_DYN>>>(x, emb, out);
    vq_final  <<<1, 32>>>(out);
}

// round 9
// speedup vs baseline: 2.7279x; 1.0389x over previous
#include <cuda_runtime.h>
#include <cuda_fp16.h>
#include <cstdint>

// -------------------------- problem constants ------------------------------
#define NN 32768        // rows (B*H*W)
#define DD 256          // embedding dim
#define KK 8192         // codebook size
#define BM 128          // rows per CTA
#define BN 256          // codes per n-tile
#define NTILES (KK / BN)            // 32
#define BSPT 8                      // B-stages per tile (4 c1-shared + 4 c2)
#define NBSTG (NTILES * BSPT)       // 256 B-stages
#define NCTA (NN / BM)              // 256

#define OUT_OFF  0
#define LOSS_OFF 8388608
#define IDX_OFF  8388609

#define A_BYTES  131072             // 8 chunks x 16 KB, resident
#define B_SLOT   32768              // one B chunk: 256 rows x 128 B
#define B_BASE   A_BYTES
#define SMEM_DYN (A_BYTES + 3 * B_SLOT)   // 229376 (<= 232448)

#define ESCALE 65536.0f             // e pre-scale 2^16 (exact)

__device__ float  g_e2[KK];
__device__ float  g_xs[NN];
__device__ double g_part[NCTA];

// fp16 operands, chunk-major [chunk][row][64 halves] (128 B/row)
// A: chunks 0-3 = h1 = fp16(x) (d 0..255), chunks 4-7 = h2 = fp16(x - h1)
// E: chunks 0-3 = c1 = fp16(e*2^16),       chunks 4-7 = c2 = fp16(e*2^16 - c1)
__device__ __align__(16) __half g_Ah[(size_t)8 * NN * 64];  // 33.5 MB
__device__ __align__(16) __half g_Eh[(size_t)8 * KK * 64];  // 8.4 MB

// ---------------------------- asm helpers ----------------------------------
__device__ __forceinline__ uint32_t smem_u32(const void* p) {
    uint32_t a;
    asm("{ .reg .u64 t; cvta.to.shared.u64 t, %1; cvt.u32.u64 %0, t; }" : "=r"(a) : "l"(p));
    return a;
}
#define CPA(dst, src) asm volatile("cp.async.cg.shared.global [%0], [%1], 16;" :: "r"(dst), "l"(src))
#define CPC()         asm volatile("cp.async.commit_group;" ::: "memory")
#define CPW(n)        asm volatile("cp.async.wait_group %0;" :: "n"(n) : "memory")

__device__ __forceinline__ void ldsm4(uint32_t* r, uint32_t addr) {
    asm volatile("ldmatrix.sync.aligned.m8n8.x4.shared.b16 {%0,%1,%2,%3}, [%4];"
        : "=r"(r[0]), "=r"(r[1]), "=r"(r[2]), "=r"(r[3]) : "r"(addr));
}
__device__ __forceinline__ void mma_fp16(float* c, const uint32_t* a, const uint32_t* b) {
    asm volatile("mma.sync.aligned.m16n8k16.row.col.f32.f16.f16.f32 "
        "{%0,%1,%2,%3}, {%4,%5,%6,%7}, {%8,%9}, {%0,%1,%2,%3};"
        : "+f"(c[0]), "+f"(c[1]), "+f"(c[2]), "+f"(c[3])
        : "r"(a[0]), "r"(a[1]), "r"(a[2]), "r"(a[3]), "r"(b[0]), "r"(b[1]));
}

// ---------------------------------------------------------------------------
// prep kernels
// ---------------------------------------------------------------------------
__global__ void vq_e2(const float* __restrict__ emb) {
    int gw = (blockIdx.x * blockDim.x + threadIdx.x) >> 5;
    int l  = threadIdx.x & 31;
    if (gw >= KK) return;
    const float* e = emb + (size_t)gw * DD;
    float s = 0.f;
#pragma unroll
    for (int t = 0; t < DD / 32; t++) { float v = e[l + 32 * t]; s = fmaf(v, v, s); }
#pragma unroll
    for (int o = 16; o > 0; o >>= 1) s += __shfl_xor_sync(0xffffffffu, s, o);
    if (l == 0) g_e2[gw] = s;
}

__global__ void vq_xs(const float* __restrict__ x) {
    int n = blockIdx.x * blockDim.x + threadIdx.x;
    if (n >= NN) return;
    int b = n >> 10, c = n & 1023;
    const float* xb = x + (size_t)b * (DD * 1024) + c;
    float s = 0.f;
#pragma unroll 8
    for (int d = 0; d < DD; d++) { float v = xb[(size_t)d * 1024]; s = fmaf(v, v, s); }
    g_xs[n] = s;
}

// x split: grid 1024 = 8 d-slices(32) x 128 row-blocks(256); smem transpose
__global__ void vq_split_x(const float* __restrict__ x) {
    __shared__ float sx[32][257];
    const int t  = threadIdx.x;
    const int dc = blockIdx.x & 7;
    const int nb = blockIdx.x >> 3;
    const int n0 = nb * 256;
    const int b  = n0 >> 10, hw0 = n0 & 1023;
    const float* xb = x + (size_t)b * (DD * 1024) + (size_t)(dc * 32) * 1024 + hw0;
#pragma unroll
    for (int dd = 0; dd < 32; dd++) sx[dd][t] = xb[(size_t)dd * 1024 + t];
    __syncthreads();

    uint32_t p1[16], p2[16];
#pragma unroll
    for (int u = 0; u < 16; u++) {
        float v0 = sx[2 * u][t], v1 = sx[2 * u + 1][t];
        __half a0 = __float2half_rn(v0);
        __half a1 = __float2half_rn(v1);
        __half b0 = __float2half_rn(__fsub_rn(v0, __half2float(a0)));  // residual exact
        __half b1 = __float2half_rn(__fsub_rn(v1, __half2float(a1)));
        p1[u] = (uint32_t)__half_as_ushort(a0) | ((uint32_t)__half_as_ushort(a1) << 16);
        p2[u] = (uint32_t)__half_as_ushort(b0) | ((uint32_t)__half_as_ushort(b1) << 16);
    }
    __half* d1 = g_Ah + ((size_t)(dc >> 1) * NN + n0 + t) * 64 + (dc & 1) * 32;
    __half* d2 = g_Ah + ((size_t)(4 + (dc >> 1)) * NN + n0 + t) * 64 + (dc & 1) * 32;
#pragma unroll
    for (int p = 0; p < 4; p++) {
        *(uint4*)(d1 + 8 * p) = make_uint4(p1[4 * p], p1[4 * p + 1], p1[4 * p + 2], p1[4 * p + 3]);
        *(uint4*)(d2 + 8 * p) = make_uint4(p2[4 * p], p2[4 * p + 1], p2[4 * p + 2], p2[4 * p + 3]);
    }
}

// emb split: 1 warp per code row; e scaled by 2^16 (exact)
__global__ void vq_split_e(const float* __restrict__ emb) {
    int wid = threadIdx.x >> 5, lane = threadIdx.x & 31;
    int k = blockIdx.x * 8 + wid;
    const float* er = emb + (size_t)k * DD;
#pragma unroll
    for (int dc = 0; dc < 8; dc++) {
        float es = __fmul_rn(er[dc * 32 + lane], ESCALE);  // exact scaling
        __half c1 = __float2half_rn(es);
        __half c2 = __float2half_rn(__fsub_rn(es, __half2float(c1)));  // residual exact
        g_Eh[((size_t)(dc >> 1) * KK + k) * 64 + (dc & 1) * 32 + lane] = c1;
        g_Eh[((size_t)(4 + (dc >> 1)) * KK + k) * 64 + (dc & 1) * 32 + lane] = c2;
    }
}

// ---------------------------------------------------------------------------
// issue helpers (XOR-swizzled 16B granules)
// ---------------------------------------------------------------------------
// A prologue: all 8 chunks (128 KB), 32 granules per thread
__device__ __forceinline__ void issueA(uint32_t sb, int rt, int tid) {
#pragma unroll
    for (int p = 0; p < 32; p++) {
        int i = tid + p * 256;
        int chunk = i >> 10, gi = i & 1023, row = gi >> 3, gg = gi & 7;
        const char* src = (const char*)g_Ah +
            ((size_t)chunk * NN + (size_t)rt * BM + row) * 128 + gg * 16;
        CPA(sb + chunk * 16384 + row * 128 + ((gg ^ (row & 7)) << 4), src);
    }
}
// one B chunk (32 KB), 8 granules per thread. B-stage g: tile g>>3, chunk g&7
__device__ __forceinline__ void issueB(uint32_t sb, int slot, int g, int tid) {
    const int ti = g >> 3, bc = g & 7;
    const char* bSrc = (const char*)g_Eh + ((size_t)bc * KK + (size_t)ti * BN) * 128;
    const uint32_t bDst = sb + B_BASE + slot * B_SLOT;
#pragma unroll
    for (int p = 0; p < 8; p++) {
        int i = tid + p * 256, row = i >> 3, gg = i & 7;
        CPA(bDst + row * 128 + ((gg ^ (row & 7)) << 4), bSrc + (size_t)i * 16);
    }
}

// ---------------------------------------------------------------------------
// consume: NA A-chunks against one B chunk (B fragments loaded once)
// ---------------------------------------------------------------------------
template <int NA>
__device__ __forceinline__ void consume(const uint32_t* aS, uint32_t bS,
                                        int wm, int wn, int lane,
                                        float (&acc)[4][8][4]) {
    const int grp = lane >> 3;
#pragma unroll
    for (int ks = 0; ks < 4; ks++) {
        uint32_t bfr[8][2];
#pragma unroll
        for (int nf2 = 0; nf2 < 4; nf2++) {
            int row = wn * 64 + nf2 * 16 + (lane & 7) + (grp >> 1) * 8;
            int gg  = 2 * ks + (grp & 1);
            uint32_t r[4];
            ldsm4(r, bS + row * 128 + ((gg ^ (row & 7)) << 4));
            bfr[2 * nf2][0] = r[0]; bfr[2 * nf2][1] = r[1];
            bfr[2 * nf2 + 1][0] = r[2]; bfr[2 * nf2 + 1][1] = r[3];
        }
#pragma unroll
        for (int u = 0; u < NA; u++) {
            uint32_t a[4][4];
#pragma unroll
            for (int mf = 0; mf < 4; mf++) {
                int row = wm * 64 + mf * 16 + (lane & 7) + (grp & 1) * 8;
                int gg  = 2 * ks + (grp >> 1);
                ldsm4(a[mf], aS[u] + row * 128 + ((gg ^ (row & 7)) << 4));
            }
#pragma unroll
            for (int mf = 0; mf < 4; mf++)
#pragma unroll
                for (int nf = 0; nf < 8; nf++)
                    mma_fp16(acc[mf][nf], a[mf], bfr[nf]);
        }
    }
}

// ---------------------------------------------------------------------------
// main fused kernel
// ---------------------------------------------------------------------------
__global__ void __launch_bounds__(256)
vq_main(const float* __restrict__ x, const float* __restrict__ emb,
        float* __restrict__ out)
{
    extern __shared__ __align__(16) char smem[];
    const uint32_t sb = smem_u32(smem);
    const int tid = threadIdx.x, lane = tid & 31, wid = tid >> 5;
    const int wm = wid & 1, wn = wid >> 1;            // 2m x 4n warps
    const int rt = blockIdx.x;
    const int n0 = rt * BM, b = n0 >> 10, col0 = n0 & 1023;

    float xs8[8];
#pragma unroll
    for (int mf = 0; mf < 4; mf++)
#pragma unroll
        for (int h = 0; h < 2; h++)
            xs8[mf * 2 + h] = g_xs[n0 + wm * 64 + mf * 16 + (lane >> 2) + 8 * h];

    float acc[4][8][4];
#pragma unroll
    for (int mf = 0; mf < 4; mf++)
#pragma unroll
        for (int nf = 0; nf < 8; nf++)
#pragma unroll
            for (int r = 0; r < 4; r++) acc[mf][nf][r] = 0.f;

    float best_v[8]; int best_i[8];
#pragma unroll
    for (int s = 0; s < 8; s++) { best_v[s] = __int_as_float(0x7f800000); best_i[s] = 0; }

    float2 e2f[8];

    // prologue: group0 = A(all) + B0, group1 = B1
    issueA(sb, rt, tid); issueB(sb, 0, 0, tid); CPC();
    issueB(sb, 1, 1, tid); CPC();

#pragma unroll 1
    for (int g = 0; g < NBSTG; g++) {
        CPW(1);                 // B_g (and A on first iter) complete
        __syncthreads();
        if (g + 2 < NBSTG) { issueB(sb, (g + 2) % 3, g + 2, tid); CPC(); }

        const int ti = g >> 3, j = g & 7;
        const int k0 = ti * BN;
        if (j == 0) {
#pragma unroll
            for (int nf = 0; nf < 8; nf++)
                e2f[nf] = *(const float2*)&g_e2[k0 + wn * 64 + nf * 8 + 2 * (lane & 3)];
        }

        const uint32_t bS = sb + B_BASE + (g % 3) * B_SLOT;
        if (j < 4) {            // B = c1 chunk j: h1*c1 and h2*c1 share it
            uint32_t aS[2] = { sb + (uint32_t)j * 16384, sb + (uint32_t)(4 + j) * 16384 };
            consume<2>(aS, bS, wm, wn, lane, acc);
        } else {                // B = c2 chunk (j-4): h1*c2
            uint32_t aS[1] = { sb + (uint32_t)(j - 4) * 16384 };
            consume<1>(aS, bS, wm, wn, lane, acc);
        }

        if (j == BSPT - 1) {
            // acc = dot * 2^16;  dist = fl( fl(xs+e2) - 2*dot ) == fmaf(-2^-15, acc, t)
#pragma unroll
            for (int mf = 0; mf < 4; mf++)
#pragma unroll
                for (int h = 0; h < 2; h++) {
                    const int s = mf * 2 + h;
                    const float xsv = xs8[s];
                    float bv = best_v[s]; int bi = best_i[s];
#pragma unroll
                    for (int nf = 0; nf < 8; nf++) {
                        float v0 = __fmaf_rn(-0x1p-15f, acc[mf][nf][h * 2 + 0], __fadd_rn(xsv, e2f[nf].x));
                        float v1 = __fmaf_rn(-0x1p-15f, acc[mf][nf][h * 2 + 1], __fadd_rn(xsv, e2f[nf].y));
                        int k = k0 + wn * 64 + nf * 8 + 2 * (lane & 3);
                        if (v0 < bv) { bv = v0; bi = k; }
                        if (v1 < bv) { bv = v1; bi = k + 1; }
                    }
                    best_v[s] = bv; best_i[s] = bi;
                }
#pragma unroll
            for (int mf = 0; mf < 4; mf++)
#pragma unroll
                for (int nf = 0; nf < 8; nf++)
#pragma unroll
                    for (int r = 0; r < 4; r++) acc[mf][nf][r] = 0.f;
        }
    }

    // ---- cross-thread argmin reduction (16 owners per row, idx-aware) -----
    // reuse A region of smem (all consumes done)
    __syncthreads();
    float* rv   = (float*)smem;                 // 128*16 floats
    int*   ri   = (int*)(smem + 8192);          // 128*16 ints
    int*   sidx = (int*)(smem + 16384);         // 128 ints
    const int owner = wn * 4 + (lane & 3);
#pragma unroll
    for (int mf = 0; mf < 4; mf++)
#pragma unroll
        for (int h = 0; h < 2; h++) {
            int row = wm * 64 + mf * 16 + (lane >> 2) + 8 * h;
            rv[row * 16 + owner] = best_v[mf * 2 + h];
            ri[row * 16 + owner] = best_i[mf * 2 + h];
        }
    __syncthreads();
    if (tid < BM) {
        float bv = rv[tid * 16]; int bi = ri[tid * 16];
#pragma unroll
        for (int o = 1; o < 16; o++) {
            float v = rv[tid * 16 + o]; int ii = ri[tid * 16 + o];
            bool p = (v < bv) || (v == bv && ii < bi);
            bv = p ? v : bv; bi = p ? ii : bi;
        }
        sidx[tid] = bi;
        out[IDX_OFF + n0 + tid] = (float)bi;
    }
    __syncthreads();

    // ---- gather + straight-through out + loss partial ---------------------
    const int r  = tid & 127;
    const int dh = tid >> 7;
    const int er = sidx[r];
    const float* embrow = emb + (size_t)er * DD;
    const float* xr   = x + (size_t)b * (DD * 1024) + col0 + r;
    float*       outr = out + OUT_OFF + (size_t)b * (DD * 1024) + col0 + r;
    double lsum = 0.0;
#pragma unroll 4
    for (int dj = 0; dj < 128; dj++) {
        int d = dh * 128 + dj;
        float xp = xr[(size_t)d * 1024];
        float q  = embrow[d];
        float dl = __fsub_rn(q, xp);
        outr[(size_t)d * 1024] = __fadd_rn(xp, dl);
        lsum += (double)__fmul_rn(dl, dl);
    }

    __syncthreads();
    double* dr = (double*)(smem + 17408);
    dr[tid] = lsum;
    __syncthreads();
    for (int sft = 128; sft > 0; sft >>= 1) {
        if (tid < sft) dr[tid] += dr[tid + sft];
        __syncthreads();
    }
    if (tid == 0) g_part[blockIdx.x] = dr[0];
}

// ---------------------------------------------------------------------------
// finalize loss
// ---------------------------------------------------------------------------
__global__ void vq_final(float* __restrict__ out) {
    if (blockIdx.x == 0 && threadIdx.x == 0) {
        double s = 0.0;
        for (int i = 0; i < NCTA; i++) s += g_part[i];
        float L = (float)(s / (double)((size_t)NN * DD));
        out[LOSS_OFF] = __fadd_rn(L, __fmul_rn(0.25f, L));
    }
}

extern "C" void kernel_launch(void* const* d_in, const int* in_sizes, int n_in,
                              void* d_out, int out_size) {
    const float* x   = (const float*)d_in[0];
    const float* emb = (const float*)d_in[1];
    float* out = (float*)d_out;

    cudaFuncSetAttribute(vq_main, cudaFuncAttributeMaxDynamicSharedMemorySize, SMEM_DYN);

    vq_e2     <<<KK * 32 / 256, 256>>>(emb);
    vq_xs     <<<NN / 256,      256>>>(x);
    vq_split_x<<<1024,          256>>>(x);
    vq_split_e<<<KK / 8,        256>>>(emb);
    vq_main   <<<NCTA, 256, SMEM_DYN>>>(x, emb, out);
    vq_final  <<<1, 32>>>(out);
}

// round 10
// speedup vs baseline: 3.9577x; 1.4508x over previous
#include <cuda_runtime.h>
#include <cuda_fp16.h>
#include <cstdint>

// -------------------------- problem constants ------------------------------
#define NN 32768        // rows (B*H*W)
#define DD 256          // embedding dim
#define KK 8192         // codebook size
#define BM 128          // rows per CTA
#define BN 256          // codes per n-tile
#define NTILES (KK / BN)            // 32
#define BSPT 4                      // B-stages per tile (c1 chunks 0..3)
#define NBSTG (NTILES * BSPT)       // 128
#define NCTA (NN / BM)              // 256

#define OUT_OFF  0
#define LOSS_OFF 8388608
#define IDX_OFF  8388609

#define A_BYTES  65536              // 4 h1 chunks x 16 KB, resident
#define B_SLOT   32768              // one c1 chunk: 256 rows x 128 B
#define B_BASE   A_BYTES
#define SMEM_DYN (A_BYTES + 3 * B_SLOT)   // 163840

#define ESCALE 65536.0f             // e pre-scale 2^16 (exact)
#define FINF   __int_as_float(0x7f800000)

__device__ float  g_e2[KK];
__device__ float  g_xs[NN];
__device__ double g_part[NCTA];
__device__ int    g_cand[NN * 8];
__device__ int    g_fidx[NN];
__device__ __align__(16) float  g_xT[(size_t)NN * DD];      // row-major x copy
// fp16 main-term operands, chunk-major [chunk][row][64 halves] (128 B/row)
__device__ __align__(16) __half g_Ah[(size_t)4 * NN * 64];  // h1 = fp16(x)
__device__ __align__(16) __half g_Eh[(size_t)4 * KK * 64];  // c1 = fp16(e*2^16)

// ---------------------------- asm helpers ----------------------------------
__device__ __forceinline__ uint32_t smem_u32(const void* p) {
    uint32_t a;
    asm("{ .reg .u64 t; cvta.to.shared.u64 t, %1; cvt.u32.u64 %0, t; }" : "=r"(a) : "l"(p));
    return a;
}
#define CPA(dst, src) asm volatile("cp.async.cg.shared.global [%0], [%1], 16;" :: "r"(dst), "l"(src))
#define CPC()         asm volatile("cp.async.commit_group;" ::: "memory")
#define CPW(n)        asm volatile("cp.async.wait_group %0;" :: "n"(n) : "memory")

__device__ __forceinline__ void ldsm4(uint32_t* r, uint32_t addr) {
    asm volatile("ldmatrix.sync.aligned.m8n8.x4.shared.b16 {%0,%1,%2,%3}, [%4];"
        : "=r"(r[0]), "=r"(r[1]), "=r"(r[2]), "=r"(r[3]) : "r"(addr));
}
__device__ __forceinline__ void mma_fp16(float* c, const uint32_t* a, const uint32_t* b) {
    asm volatile("mma.sync.aligned.m16n8k16.row.col.f32.f16.f16.f32 "
        "{%0,%1,%2,%3}, {%4,%5,%6,%7}, {%8,%9}, {%0,%1,%2,%3};"
        : "+f"(c[0]), "+f"(c[1]), "+f"(c[2]), "+f"(c[3])
        : "r"(a[0]), "r"(a[1]), "r"(a[2]), "r"(a[3]), "r"(b[0]), "r"(b[1]));
}

// ---------------------------------------------------------------------------
// prep kernels
// ---------------------------------------------------------------------------
__global__ void vq_e2(const float* __restrict__ emb) {
    int gw = (blockIdx.x * blockDim.x + threadIdx.x) >> 5;
    int l  = threadIdx.x & 31;
    if (gw >= KK) return;
    const float* e = emb + (size_t)gw * DD;
    float s = 0.f;
#pragma unroll
    for (int t = 0; t < DD / 32; t++) { float v = e[l + 32 * t]; s = fmaf(v, v, s); }
#pragma unroll
    for (int o = 16; o > 0; o >>= 1) s += __shfl_xor_sync(0xffffffffu, s, o);
    if (l == 0) g_e2[gw] = s;
}

__global__ void vq_xs(const float* __restrict__ x) {
    int n = blockIdx.x * blockDim.x + threadIdx.x;
    if (n >= NN) return;
    int b = n >> 10, c = n & 1023;
    const float* xb = x + (size_t)b * (DD * 1024) + c;
    float s = 0.f;
#pragma unroll 8
    for (int d = 0; d < DD; d++) { float v = xb[(size_t)d * 1024]; s = fmaf(v, v, s); }
    g_xs[n] = s;
}

// x split: grid 1024 = 8 d-slices(32) x 128 row-blocks(256); smem transpose
// produces: h1 fp16 chunks AND g_xT (row-major fp32 x)
__global__ void vq_split_x(const float* __restrict__ x) {
    __shared__ float sx[32][257];
    const int t  = threadIdx.x;
    const int dc = blockIdx.x & 7;
    const int nb = blockIdx.x >> 3;
    const int n0 = nb * 256;
    const int b  = n0 >> 10, hw0 = n0 & 1023;
    const float* xb = x + (size_t)b * (DD * 1024) + (size_t)(dc * 32) * 1024 + hw0;
#pragma unroll
    for (int dd = 0; dd < 32; dd++) sx[dd][t] = xb[(size_t)dd * 1024 + t];
    __syncthreads();

    // row-major fp32 copy
    float* xrow = g_xT + (size_t)(n0 + t) * DD + dc * 32;
#pragma unroll
    for (int q = 0; q < 8; q++)
        *(float4*)(xrow + 4 * q) = make_float4(sx[4 * q][t], sx[4 * q + 1][t],
                                               sx[4 * q + 2][t], sx[4 * q + 3][t]);
    // h1 fp16 chunk
    uint32_t p1[16];
#pragma unroll
    for (int u = 0; u < 16; u++) {
        uint32_t h0 = (uint32_t)__half_as_ushort(__float2half_rn(sx[2 * u][t]));
        uint32_t h1 = (uint32_t)__half_as_ushort(__float2half_rn(sx[2 * u + 1][t]));
        p1[u] = h0 | (h1 << 16);
    }
    __half* d1 = g_Ah + ((size_t)(dc >> 1) * NN + n0 + t) * 64 + (dc & 1) * 32;
#pragma unroll
    for (int p = 0; p < 4; p++)
        *(uint4*)(d1 + 8 * p) = make_uint4(p1[4 * p], p1[4 * p + 1], p1[4 * p + 2], p1[4 * p + 3]);
}

// emb split: 1 warp per code row; c1 = fp16(e*2^16)
__global__ void vq_split_e(const float* __restrict__ emb) {
    int wid = threadIdx.x >> 5, lane = threadIdx.x & 31;
    int k = blockIdx.x * 8 + wid;
    const float* er = emb + (size_t)k * DD;
#pragma unroll
    for (int dc = 0; dc < 8; dc++) {
        float es = __fmul_rn(er[dc * 32 + lane], ESCALE);  // exact scaling
        g_Eh[((size_t)(dc >> 1) * KK + k) * 64 + (dc & 1) * 32 + lane] = __float2half_rn(es);
    }
}

// ---------------------------------------------------------------------------
// issue helpers (XOR-swizzled 16B granules)
// ---------------------------------------------------------------------------
__device__ __forceinline__ void issueA(uint32_t sb, int rt, int tid) {
#pragma unroll
    for (int p = 0; p < 16; p++) {
        int i = tid + p * 256;
        int chunk = i >> 10, gi = i & 1023, row = gi >> 3, gg = gi & 7;
        const char* src = (const char*)g_Ah +
            ((size_t)chunk * NN + (size_t)rt * BM + row) * 128 + gg * 16;
        CPA(sb + chunk * 16384 + row * 128 + ((gg ^ (row & 7)) << 4), src);
    }
}
// B-stage g: tile g>>2, c1 chunk g&3
__device__ __forceinline__ void issueB(uint32_t sb, int slot, int g, int tid) {
    const int ti = g >> 2, bc = g & 3;
    const char* bSrc = (const char*)g_Eh + ((size_t)bc * KK + (size_t)ti * BN) * 128;
    const uint32_t bDst = sb + B_BASE + slot * B_SLOT;
#pragma unroll
    for (int p = 0; p < 8; p++) {
        int i = tid + p * 256, row = i >> 3, gg = i & 7;
        CPA(bDst + row * 128 + ((gg ^ (row & 7)) << 4), bSrc + (size_t)i * 16);
    }
}

// consume: one A chunk vs one B chunk
__device__ __forceinline__ void consume(uint32_t aS, uint32_t bS, int wm, int wn,
                                        int lane, float (&acc)[4][8][4]) {
    const int grp = lane >> 3;
#pragma unroll
    for (int ks = 0; ks < 4; ks++) {
        uint32_t bfr[8][2];
#pragma unroll
        for (int nf2 = 0; nf2 < 4; nf2++) {
            int row = wn * 64 + nf2 * 16 + (lane & 7) + (grp >> 1) * 8;
            int gg  = 2 * ks + (grp & 1);
            uint32_t r[4];
            ldsm4(r, bS + row * 128 + ((gg ^ (row & 7)) << 4));
            bfr[2 * nf2][0] = r[0]; bfr[2 * nf2][1] = r[1];
            bfr[2 * nf2 + 1][0] = r[2]; bfr[2 * nf2 + 1][1] = r[3];
        }
        uint32_t a[4][4];
#pragma unroll
        for (int mf = 0; mf < 4; mf++) {
            int row = wm * 64 + mf * 16 + (lane & 7) + (grp & 1) * 8;
            int gg  = 2 * ks + (grp >> 1);
            ldsm4(a[mf], aS + row * 128 + ((gg ^ (row & 7)) << 4));
        }
#pragma unroll
        for (int mf = 0; mf < 4; mf++)
#pragma unroll
            for (int nf = 0; nf < 8; nf++)
                mma_fp16(acc[mf][nf], a[mf], bfr[nf]);
    }
}

// ---------------------------------------------------------------------------
// pass-1 main: approx distances (h1*c1) + best-3/slot + top-8/row candidates
// ---------------------------------------------------------------------------
__global__ void __launch_bounds__(256)
vq_main() {
    extern __shared__ __align__(16) char smem[];
    const uint32_t sb = smem_u32(smem);
    const int tid = threadIdx.x, lane = tid & 31, wid = tid >> 5;
    const int wm = wid & 1, wn = wid >> 1;
    const int rt = blockIdx.x;
    const int n0 = rt * BM;

    float xs8[8];
#pragma unroll
    for (int mf = 0; mf < 4; mf++)
#pragma unroll
        for (int h = 0; h < 2; h++)
            xs8[mf * 2 + h] = g_xs[n0 + wm * 64 + mf * 16 + (lane >> 2) + 8 * h];

    float acc[4][8][4];
#pragma unroll
    for (int mf = 0; mf < 4; mf++)
#pragma unroll
        for (int nf = 0; nf < 8; nf++)
#pragma unroll
            for (int r = 0; r < 4; r++) acc[mf][nf][r] = 0.f;

    // best-3 per row-slot
    float b1v[8], b2v[8], b3v[8]; int b1i[8], b2i[8], b3i[8];
#pragma unroll
    for (int s = 0; s < 8; s++) {
        b1v[s] = FINF; b2v[s] = FINF; b3v[s] = FINF;
        b1i[s] = 0; b2i[s] = 0; b3i[s] = 0;
    }

    float2 e2f[8];

    issueA(sb, rt, tid); issueB(sb, 0, 0, tid); CPC();
    issueB(sb, 1, 1, tid); CPC();

#pragma unroll 1
    for (int g = 0; g < NBSTG; g++) {
        CPW(1);
        __syncthreads();
        if (g + 2 < NBSTG) { issueB(sb, (g + 2) % 3, g + 2, tid); CPC(); }

        const int ti = g >> 2, j = g & 3;
        const int k0 = ti * BN;
        if (j == 0) {
#pragma unroll
            for (int nf = 0; nf < 8; nf++)
                e2f[nf] = *(const float2*)&g_e2[k0 + wn * 64 + nf * 8 + 2 * (lane & 3)];
        }

        consume(sb + (uint32_t)j * 16384, sb + B_BASE + (g % 3) * B_SLOT, wm, wn, lane, acc);

        if (j == 3) {
            // approx v = fmaf(-2^-15, acc, fl(xs+e2)); best-3 insertion, ascending k
#pragma unroll
            for (int mf = 0; mf < 4; mf++)
#pragma unroll
                for (int h = 0; h < 2; h++) {
                    const int s = mf * 2 + h;
                    const float xsv = xs8[s];
#pragma unroll
                    for (int nf = 0; nf < 8; nf++) {
#pragma unroll
                        for (int q = 0; q < 2; q++) {
                            float e2v = q ? e2f[nf].y : e2f[nf].x;
                            float v = __fmaf_rn(-0x1p-15f, acc[mf][nf][h * 2 + q], __fadd_rn(xsv, e2v));
                            int k = k0 + wn * 64 + nf * 8 + 2 * (lane & 3) + q;
                            if (v < b3v[s]) {
                                if (v < b1v[s]) {
                                    b3v[s] = b2v[s]; b3i[s] = b2i[s];
                                    b2v[s] = b1v[s]; b2i[s] = b1i[s];
                                    b1v[s] = v; b1i[s] = k;
                                } else if (v < b2v[s]) {
                                    b3v[s] = b2v[s]; b3i[s] = b2i[s];
                                    b2v[s] = v; b2i[s] = k;
                                } else {
                                    b3v[s] = v; b3i[s] = k;
                                }
                            }
                        }
                    }
                }
#pragma unroll
            for (int mf = 0; mf < 4; mf++)
#pragma unroll
                for (int nf = 0; nf < 8; nf++)
#pragma unroll
                    for (int r = 0; r < 4; r++) acc[mf][nf][r] = 0.f;
        }
    }

    // dump 48 candidates/row to smem, then per-row top-8 select
    __syncthreads();
    float* rv = (float*)smem;            // 128*48 floats = 24 KB
    int*   ri = (int*)(smem + 24576);    // 24 KB
    const int owner = wn * 4 + (lane & 3);
#pragma unroll
    for (int mf = 0; mf < 4; mf++)
#pragma unroll
        for (int h = 0; h < 2; h++) {
            int row = wm * 64 + mf * 16 + (lane >> 2) + 8 * h;
            int s = mf * 2 + h;
            int base = row * 48 + owner * 3;
            rv[base + 0] = b1v[s]; ri[base + 0] = b1i[s];
            rv[base + 1] = b2v[s]; ri[base + 1] = b2i[s];
            rv[base + 2] = b3v[s]; ri[base + 2] = b3i[s];
        }
    __syncthreads();
    if (tid < BM) {
        const int base = tid * 48;
#pragma unroll 1
        for (int c = 0; c < 8; c++) {
            float bv = FINF; int bi = 0x7fffffff, bj = 0;
            for (int t = 0; t < 48; t++) {
                float v = rv[base + t]; int ii = ri[base + t];
                if (v < bv || (v == bv && ii < bi)) { bv = v; bi = ii; bj = t; }
            }
            g_cand[(size_t)(n0 + tid) * 8 + c] = bi;
            rv[base + bj] = FINF; ri[base + bj] = 0x7fffffff;
        }
    }
}

// ---------------------------------------------------------------------------
// pass-2: exact fp32 distance on 8 candidates/row; pick final idx
// ---------------------------------------------------------------------------
__global__ void vq_exact(const float* __restrict__ emb, float* __restrict__ out) {
    const int w = threadIdx.x >> 5, lane = threadIdx.x & 31;
    const int n = blockIdx.x * 8 + w;
    const float* xr = g_xT + (size_t)n * DD;
    float xv[8];
#pragma unroll
    for (int t = 0; t < 8; t++) xv[t] = xr[lane + 32 * t];
    const float xs = g_xs[n];
    float bv = FINF; int bi = 0x7fffffff;
#pragma unroll 1
    for (int c = 0; c < 8; c++) {
        int k = g_cand[(size_t)n * 8 + c];
        const float* er = emb + (size_t)k * DD;
        float dot = 0.f;
#pragma unroll
        for (int t = 0; t < 8; t++) dot = fmaf(xv[t], er[lane + 32 * t], dot);
#pragma unroll
        for (int o = 16; o > 0; o >>= 1) dot += __shfl_xor_sync(0xffffffffu, dot, o);
        float t0 = __fadd_rn(xs, g_e2[k]);
        float v  = __fsub_rn(t0, __fadd_rn(dot, dot));
        if (v < bv || (v == bv && k < bi)) { bv = v; bi = k; }
    }
    if (lane == 0) {
        g_fidx[n] = bi;
        out[IDX_OFF + n] = (float)bi;
    }
}

// ---------------------------------------------------------------------------
// finalize: gather + straight-through out + loss partial
// ---------------------------------------------------------------------------
__global__ void vq_fin(const float* __restrict__ x, const float* __restrict__ emb,
                       float* __restrict__ out) {
    __shared__ double dr[256];
    const int tid = threadIdx.x;
    const int n0 = blockIdx.x * BM, b = n0 >> 10, col0 = n0 & 1023;
    const int r  = tid & 127;
    const int dh = tid >> 7;
    const int er = g_fidx[n0 + r];
    const float* embrow = emb + (size_t)er * DD;
    const float* xr   = x + (size_t)b * (DD * 1024) + col0 + r;
    float*       outr = out + OUT_OFF + (size_t)b * (DD * 1024) + col0 + r;
    double lsum = 0.0;
#pragma unroll 4
    for (int dj = 0; dj < 128; dj++) {
        int d = dh * 128 + dj;
        float xp = xr[(size_t)d * 1024];
        float q  = embrow[d];
        float dl = __fsub_rn(q, xp);
        outr[(size_t)d * 1024] = __fadd_rn(xp, dl);
        lsum += (double)__fmul_rn(dl, dl);
    }
    dr[tid] = lsum;
    __syncthreads();
    for (int sft = 128; sft > 0; sft >>= 1) {
        if (tid < sft) dr[tid] += dr[tid + sft];
        __syncthreads();
    }
    if (tid == 0) g_part[blockIdx.x] = dr[0];
}

// ---------------------------------------------------------------------------
// finalize loss (one warp, deterministic)
// ---------------------------------------------------------------------------
__global__ void vq_final(float* __restrict__ out) {
    int l = threadIdx.x;
    double s = 0.0;
    for (int i = l; i < NCTA; i += 32) s += g_part[i];
#pragma unroll
    for (int o = 16; o > 0; o >>= 1) s += __shfl_xor_sync(0xffffffffu, s, o);
    if (l == 0) {
        float L = (float)(s / (double)((size_t)NN * DD));
        out[LOSS_OFF] = __fadd_rn(L, __fmul_rn(0.25f, L));
    }
}

extern "C" void kernel_launch(void* const* d_in, const int* in_sizes, int n_in,
                              void* d_out, int out_size) {
    const float* x   = (const float*)d_in[0];
    const float* emb = (const float*)d_in[1];
    float* out = (float*)d_out;

    cudaFuncSetAttribute(vq_main, cudaFuncAttributeMaxDynamicSharedMemorySize, SMEM_DYN);

    vq_e2     <<<KK * 32 / 256, 256>>>(emb);
    vq_xs     <<<NN / 256,      256>>>(x);
    vq_split_x<<<1024,          256>>>(x);
    vq_split_e<<<KK / 8,        256>>>(emb);
    vq_main   <<<NCTA, 256, SMEM_DYN>>>();
    vq_exact  <<<NN / 8, 256>>>(emb, out);
    vq_fin    <<<NCTA, 256>>>(x, emb, out);
    vq_final  <<<1, 32>>>(out);
}